// round 7
// baseline (speedup 1.0000x reference)
#include <cuda_runtime.h>
#include <cstdint>

#define Bv 256
#define Tv 512
#define Iv 128
#define Hv 256
#define G4v 1024
#define GRPS 16   // batch groups (one cluster each)
#define CLS 8     // cluster size = hidden slices per group
#define MBr 16    // batch rows per group
#define HSc 32    // hidden cols per CTA slice

// ---------------- scratch (device globals; no cudaMalloc allowed) ----------
__device__ float g_xg[(long long)Tv * Bv * G4v];    // gate preacts [t][b][4H]
__device__ float g_hseq[(long long)Tv * Bv * Hv];   // layer0 output [t][b][H]
__device__ float g_hfinal[Bv * Hv];                 // final hidden state for FC

// ---------------- helpers ---------------------------------------------------
__device__ __forceinline__ unsigned f2tf(float f) {
    unsigned u;
    asm("cvt.rna.tf32.f32 %0, %1;" : "=r"(u) : "f"(f));
    return u;
}
__device__ __forceinline__ void mma_tf32(float c[4], unsigned a0, unsigned a1,
                                         unsigned a2, unsigned a3,
                                         unsigned b0, unsigned b1) {
    asm volatile(
        "mma.sync.aligned.m16n8k8.row.col.f32.tf32.tf32.f32 "
        "{%0,%1,%2,%3}, {%4,%5,%6,%7}, {%8,%9}, {%0,%1,%2,%3};"
        : "+f"(c[0]), "+f"(c[1]), "+f"(c[2]), "+f"(c[3])
        : "r"(a0), "r"(a1), "r"(a2), "r"(a3), "r"(b0), "r"(b1));
}
__device__ __forceinline__ float tanhfast(float x) {
    float y;
    asm("tanh.approx.f32 %0, %1;" : "=f"(y) : "f"(x));
    return y;
}
__device__ __forceinline__ float sigm(float x) {
    return fmaf(0.5f, tanhfast(0.5f * x), 0.5f);
}
__device__ __forceinline__ uint32_t smem_u32(const void* p) {
    uint32_t a;
    asm("{ .reg .u64 t; cvta.to.shared.u64 t, %1; cvt.u32.u64 %0, t; }"
        : "=r"(a) : "l"(p));
    return a;
}
__device__ __forceinline__ uint32_t mapa_u32(uint32_t addr, uint32_t rank) {
    uint32_t r;
    asm("mapa.shared::cluster.u32 %0, %1, %2;" : "=r"(r) : "r"(addr), "r"(rank));
    return r;
}
__device__ __forceinline__ void st_cluster_u32(uint32_t addr, uint32_t v) {
    asm volatile("st.shared::cluster.u32 [%0], %1;" :: "r"(addr), "r"(v) : "memory");
}
__device__ __forceinline__ void mbar_init(uint32_t addr, uint32_t cnt) {
    asm volatile("mbarrier.init.shared.b64 [%0], %1;" :: "r"(addr), "r"(cnt) : "memory");
}
__device__ __forceinline__ void mbar_arrive_remote(uint32_t addr) {
    asm volatile("mbarrier.arrive.release.cluster.shared::cluster.b64 _, [%0];"
                 :: "r"(addr) : "memory");
}
__device__ __forceinline__ void mbar_wait(uint32_t addr, uint32_t parity) {
    uint32_t done;
    asm volatile(
        "{\n\t.reg .pred p;\n\t"
        "mbarrier.try_wait.parity.acquire.cluster.shared::cta.b64 p, [%1], %2;\n\t"
        "selp.b32 %0, 1, 0, p;\n\t}"
        : "=r"(done) : "r"(addr), "r"(parity) : "memory");
    while (!done) {
        asm volatile(
            "{\n\t.reg .pred p;\n\t"
            "mbarrier.try_wait.parity.acquire.cluster.shared::cta.b64 p, [%1], %2, 0x989680;\n\t"
            "selp.b32 %0, 1, 0, p;\n\t}"
            : "=r"(done) : "r"(addr), "r"(parity) : "memory");
    }
}

// ---------------- input-projection GEMM (tf32 mma) -------------------------
__global__ void __launch_bounds__(256) gemm_tf32(
    const float* __restrict__ A_ext, int useHseq, long long sB, long long sT, int K,
    const float* __restrict__ W, const float* __restrict__ bias1,
    const float* __restrict__ bias2)
{
    __shared__ float As[128][36];
    __shared__ float Bs[64][36];

    const float* A = useHseq ? (const float*)g_hseq : A_ext;

    int tid  = threadIdx.x;
    int lane = tid & 31, wid = tid >> 5;
    int wm = wid & 3, wn = wid >> 2;
    int mbase = wm * 32, nbase = wn * 32;
    int grp = lane >> 2, tig = lane & 3;
    int ctaN = blockIdx.x, ctaM = blockIdx.y;

    float acc[2][4][4];
#pragma unroll
    for (int a = 0; a < 2; a++)
#pragma unroll
        for (int b = 0; b < 4; b++)
#pragma unroll
            for (int c = 0; c < 4; c++) acc[a][b][c] = 0.0f;

    for (int k0 = 0; k0 < K; k0 += 32) {
#pragma unroll
        for (int i = 0; i < 4; i++) {
            int id = tid + i * 256;
            int r = id >> 3, c4 = id & 7;
            long long grow = (long long)ctaM * 128 + r;
            const float* src = A + (grow & (Bv - 1)) * sB + (grow >> 8) * sT + k0 + c4 * 4;
            float4 v = *(const float4*)src;
            As[r][c4 * 4 + 0] = __uint_as_float(f2tf(v.x));
            As[r][c4 * 4 + 1] = __uint_as_float(f2tf(v.y));
            As[r][c4 * 4 + 2] = __uint_as_float(f2tf(v.z));
            As[r][c4 * 4 + 3] = __uint_as_float(f2tf(v.w));
        }
#pragma unroll
        for (int i = 0; i < 2; i++) {
            int id = tid + i * 256;
            int r = id >> 3, c4 = id & 7;
            const float* src = W + (long long)(ctaN * 64 + r) * K + k0 + c4 * 4;
            float4 v = *(const float4*)src;
            Bs[r][c4 * 4 + 0] = __uint_as_float(f2tf(v.x));
            Bs[r][c4 * 4 + 1] = __uint_as_float(f2tf(v.y));
            Bs[r][c4 * 4 + 2] = __uint_as_float(f2tf(v.z));
            Bs[r][c4 * 4 + 3] = __uint_as_float(f2tf(v.w));
        }
        __syncthreads();

#pragma unroll
        for (int kk = 0; kk < 32; kk += 8) {
            unsigned a[2][4];
#pragma unroll
            for (int mt = 0; mt < 2; mt++) {
                int row = mbase + mt * 16 + grp;
                a[mt][0] = __float_as_uint(As[row][kk + tig]);
                a[mt][1] = __float_as_uint(As[row + 8][kk + tig]);
                a[mt][2] = __float_as_uint(As[row][kk + tig + 4]);
                a[mt][3] = __float_as_uint(As[row + 8][kk + tig + 4]);
            }
#pragma unroll
            for (int nt = 0; nt < 4; nt++) {
                int nr = nbase + nt * 8 + grp;
                unsigned b0 = __float_as_uint(Bs[nr][kk + tig]);
                unsigned b1 = __float_as_uint(Bs[nr][kk + tig + 4]);
#pragma unroll
                for (int mt = 0; mt < 2; mt++)
                    mma_tf32(acc[mt][nt], a[mt][0], a[mt][1], a[mt][2], a[mt][3], b0, b1);
            }
        }
        __syncthreads();
    }

#pragma unroll
    for (int mt = 0; mt < 2; mt++) {
#pragma unroll
        for (int nt = 0; nt < 4; nt++) {
            long long grow = (long long)ctaM * 128 + mbase + mt * 16 + grp;
            int gcol = ctaN * 64 + nbase + nt * 8 + 2 * tig;
            float bb0 = bias1[gcol] + bias2[gcol];
            float bb1 = bias1[gcol + 1] + bias2[gcol + 1];
            g_xg[grow * G4v + gcol]           = acc[mt][nt][0] + bb0;
            g_xg[grow * G4v + gcol + 1]       = acc[mt][nt][1] + bb1;
            g_xg[(grow + 8) * G4v + gcol]     = acc[mt][nt][2] + bb0;
            g_xg[(grow + 8) * G4v + gcol + 1] = acc[mt][nt][3] + bb1;
        }
    }
}

// ---------------- persistent recurrence kernel (cluster DSMEM exchange) ----
// 128 CTAs = 16 clusters of 8. Cluster = one batch group (16 rows);
// rank hs (0..7) owns hidden cols [hs*32, hs*32+32).
// Per step: mma from LOCAL SMEM h copy -> gates -> epilogue -> push own
// slice into all 8 peers' SMEM (st.shared::cluster) + mbarrier arrive.
// SMEM floats: mbars(4) | gates 16x132 | hsm 2x16x4x68 | slen 16 | pmax
__global__ void __launch_bounds__(256, 1) __cluster_dims__(CLS, 1, 1)
lstm_rec(const int* __restrict__ lengths, const float* __restrict__ W_hh, int writeSeq)
{
    extern __shared__ float sm[];
    float* gates = sm + 4;                 // [16][132]
    float* hsm   = sm + 4 + 2112;          // [2][16][4][68]
    int*   slen  = (int*)(sm + 4 + 2112 + 8704);
    int*   pmax  = slen + 16;

    uint32_t smem_base = smem_u32(sm);
    uint32_t mbar0 = smem_base;            // mbar[buf] at mbar0 + buf*8
    uint32_t hsm_u32 = smem_base + (4 + 2112) * 4;

    int tid = threadIdx.x, lane = tid & 31, wid = tid >> 5;
    int group = blockIdx.x >> 3;
    int hs = blockIdx.x & 7;               // cluster rank
    int gate = wid >> 1, half = wid & 1;   // warp -> (gate, 16-col half)
    int grp = lane >> 2, tig = lane & 3;

    // ---- W_hh fragments in registers (tf32), constant over all steps
    unsigned Breg[2][64];
#pragma unroll
    for (int nt = 0; nt < 2; nt++) {
        const float* p = W_hh +
            (long long)(gate * 256 + hs * HSc + half * 16 + nt * 8 + grp) * Hv + tig;
#pragma unroll
        for (int u = 0; u < 64; u++)
            Breg[nt][u] = f2tf(__ldg(p + 4 * u));
    }

    if (tid < 16) slen[tid] = lengths[group * MBr + tid];
    if (tid == 0) {
        mbar_init(mbar0, CLS);
        mbar_init(mbar0 + 8, CLS);
    }
    __syncthreads();
    if (tid == 0) {
        int m = 0;
        for (int i = 0; i < 16; i++) m = max(m, slen[i]);
        pmax[0] = m;
    }
    __syncthreads();
    int maxlen = pmax[0];
    int mylen = slen[tid >> 4];

    // mbar init visible cluster-wide before any remote arrive
    asm volatile("barrier.cluster.arrive.aligned;" ::: "memory");
    asm volatile("barrier.cluster.wait.aligned;" ::: "memory");

    // epilogue mapping: thread owns (eb, cols jp..jp+1) of this CTA's slice
    int eb = tid >> 4;           // 0..15
    int jp = (tid & 15) * 2;     // 0,2,...,30
    float2 hmy = make_float2(0.0f, 0.0f);
    float2 cstr = make_float2(0.0f, 0.0f);

    // push byte offsets within an hsm buffer for global cols c0, c0+1
    int c0 = hs * HSc + jp;
    uint32_t off0 = (uint32_t)(eb * 272 + (c0 & 3) * 68 + (c0 >> 2)) * 4;
    uint32_t off1 = (uint32_t)(eb * 272 + ((c0 + 1) & 3) * 68 + ((c0 + 1) >> 2)) * 4;

    // xg prefetch (mma accumulator layout)
    int cb = gate * 256 + hs * HSc + half * 16 + 2 * tig;
    float2 xgp[2][2];
    {
        long long rb = (long long)(group * MBr + grp) * G4v;
#pragma unroll
        for (int nt = 0; nt < 2; nt++) {
            xgp[nt][0] = *(const float2*)(g_xg + rb + cb + nt * 8);
            xgp[nt][1] = *(const float2*)(g_xg + rb + 8 * G4v + cb + nt * 8);
        }
    }

    for (int t = 0; t < maxlen; t++) {
        // ---- 1. xg prefetch for t+1 (independent)
        float2 xgn[2][2];
        if (t + 1 < maxlen) {
            long long rb = ((long long)(t + 1) * Bv + group * MBr + grp) * G4v;
#pragma unroll
            for (int nt = 0; nt < 2; nt++) {
                xgn[nt][0] = *(const float2*)(g_xg + rb + cb + nt * 8);
                xgn[nt][1] = *(const float2*)(g_xg + rb + 8 * G4v + cb + nt * 8);
            }
        }

        // ---- 2. wait: all 8 slices of h(t-1) delivered to LOCAL SMEM
        if (t > 0)
            mbar_wait(mbar0 + ((t - 1) & 1) * 8, ((unsigned)(t - 1) >> 1) & 1);

        // ---- 3. mma from local SMEM (conflict-free LDS.128 combs)
        float acc[4][2][4];
#pragma unroll
        for (int nt = 0; nt < 2; nt++) {
            acc[0][nt][0] = xgp[nt][0].x;
            acc[0][nt][1] = xgp[nt][0].y;
            acc[0][nt][2] = xgp[nt][1].x;
            acc[0][nt][3] = xgp[nt][1].y;
#pragma unroll
            for (int ch = 1; ch < 4; ch++) {
                acc[ch][nt][0] = 0.0f; acc[ch][nt][1] = 0.0f;
                acc[ch][nt][2] = 0.0f; acc[ch][nt][3] = 0.0f;
            }
        }
        if (t > 0) {
            const float* ha = hsm + ((t - 1) & 1) * 4352 + grp * 272 + tig * 68;
            const float* hb = ha + 8 * 272;
#pragma unroll
            for (int m = 0; m < 16; m++) {
                float4 fa = *(const float4*)(ha + 4 * m);
                float4 fb = *(const float4*)(hb + 4 * m);
                int p0 = (m & 1) * 2;
                mma_tf32(acc[p0][0],
                         __float_as_uint(fa.x), __float_as_uint(fb.x),
                         __float_as_uint(fa.y), __float_as_uint(fb.y),
                         Breg[0][4 * m], Breg[0][4 * m + 1]);
                mma_tf32(acc[p0][1],
                         __float_as_uint(fa.x), __float_as_uint(fb.x),
                         __float_as_uint(fa.y), __float_as_uint(fb.y),
                         Breg[1][4 * m], Breg[1][4 * m + 1]);
                mma_tf32(acc[p0 + 1][0],
                         __float_as_uint(fa.z), __float_as_uint(fb.z),
                         __float_as_uint(fa.w), __float_as_uint(fb.w),
                         Breg[0][4 * m + 2], Breg[0][4 * m + 3]);
                mma_tf32(acc[p0 + 1][1],
                         __float_as_uint(fa.z), __float_as_uint(fb.z),
                         __float_as_uint(fa.w), __float_as_uint(fb.w),
                         Breg[1][4 * m + 2], Breg[1][4 * m + 3]);
            }
        }
        xgp[0][0] = xgn[0][0]; xgp[0][1] = xgn[0][1];
        xgp[1][0] = xgn[1][0]; xgp[1][1] = xgn[1][1];

        // ---- 4. reduce chains, write gate preacts (16 rows x 128 cols)
#pragma unroll
        for (int nt = 0; nt < 2; nt++) {
            int gc = gate * 32 + half * 16 + nt * 8 + 2 * tig;
            float v0 = acc[0][nt][0] + acc[1][nt][0] + acc[2][nt][0] + acc[3][nt][0];
            float v1 = acc[0][nt][1] + acc[1][nt][1] + acc[2][nt][1] + acc[3][nt][1];
            float v2 = acc[0][nt][2] + acc[1][nt][2] + acc[2][nt][2] + acc[3][nt][2];
            float v3 = acc[0][nt][3] + acc[1][nt][3] + acc[2][nt][3] + acc[3][nt][3];
            *(float2*)&gates[grp * 132 + gc]       = make_float2(v0, v1);
            *(float2*)&gates[(grp + 8) * 132 + gc] = make_float2(v2, v3);
        }
        __syncthreads();

        // ---- 5. activations + state update (c state in registers)
        bool act = (t < mylen);
        if (act) {
            float2 gi = *(const float2*)&gates[eb * 132 + jp];
            float2 gf = *(const float2*)&gates[eb * 132 + 32 + jp];
            float2 gg = *(const float2*)&gates[eb * 132 + 64 + jp];
            float2 go = *(const float2*)&gates[eb * 132 + 96 + jp];
            float i0 = sigm(gi.x), i1 = sigm(gi.y);
            float f0 = sigm(gf.x), f1 = sigm(gf.y);
            float g0 = tanhfast(gg.x), g1 = tanhfast(gg.y);
            float o0 = sigm(go.x), o1 = sigm(go.y);
            float cn0 = fmaf(f0, cstr.x, i0 * g0);
            float cn1 = fmaf(f1, cstr.y, i1 * g1);
            cstr = make_float2(cn0, cn1);
            hmy = make_float2(o0 * tanhfast(cn0), o1 * tanhfast(cn1));
        }

        // ---- 6. push own slice to all 8 cluster CTAs + arrive
        if (t + 1 < maxlen) {
            unsigned v0 = f2tf(hmy.x);
            unsigned v1 = f2tf(hmy.y);
            uint32_t a0 = hsm_u32 + (unsigned)(t & 1) * 4352u * 4u + off0;
            uint32_t a1 = hsm_u32 + (unsigned)(t & 1) * 4352u * 4u + off1;
#pragma unroll
            for (int r = 0; r < CLS; r++) {
                st_cluster_u32(mapa_u32(a0, r), v0);
                st_cluster_u32(mapa_u32(a1, r), v1);
            }
            __syncthreads();   // all pushes issued CTA-wide; gates reads done
            if (tid < CLS)
                mbar_arrive_remote(mapa_u32(mbar0 + (unsigned)(t & 1) * 8u, tid));
        }

        // ---- 7. hseq store (off critical path)
        if (writeSeq && act)
            *(float2*)(g_hseq + ((long long)t * Bv + group * MBr + eb) * Hv
                       + hs * HSc + jp) = hmy;
    }

    // publish final hidden state for FC
    *(float2*)(g_hfinal + (long long)(group * MBr + eb) * Hv + hs * HSc + jp) = hmy;

    // no CTA may exit while peers could still touch its SMEM
    asm volatile("barrier.cluster.arrive.aligned;" ::: "memory");
    asm volatile("barrier.cluster.wait.aligned;" ::: "memory");
}

// ---------------- final FC + softmax ----------------------------------------
__global__ void fc_softmax(const float* __restrict__ W_fc,
                           const float* __restrict__ b_fc, float* __restrict__ out)
{
    int b = blockIdx.x, lane = threadIdx.x;
    float logit[10];
#pragma unroll
    for (int c = 0; c < 10; c++) {
        float s = 0.0f;
        for (int h = lane; h < Hv; h += 32)
            s += g_hfinal[b * Hv + h] * W_fc[c * Hv + h];
#pragma unroll
        for (int o = 16; o; o >>= 1) s += __shfl_down_sync(0xffffffffu, s, o);
        logit[c] = s;
    }
    if (lane == 0) {
        float mx = -1e30f;
#pragma unroll
        for (int c = 0; c < 10; c++) {
            logit[c] += b_fc[c];
            mx = fmaxf(mx, logit[c]);
        }
        float sum = 0.0f;
#pragma unroll
        for (int c = 0; c < 10; c++) {
            logit[c] = expf(logit[c] - mx);
            sum += logit[c];
        }
        float inv = 1.0f / sum;
#pragma unroll
        for (int c = 0; c < 10; c++) out[b * 10 + c] = logit[c] * inv;
    }
}

// ---------------- host launcher ---------------------------------------------
extern "C" void kernel_launch(void* const* d_in, const int* in_sizes, int n_in,
                              void* d_out, int out_size)
{
    const float* x      = (const float*)d_in[0];
    const int*   length = (const int*)d_in[1];
    const float* W_fc   = (const float*)d_in[2];
    const float* b_fc   = (const float*)d_in[3];
    const float* W_ih0  = (const float*)d_in[4];
    const float* W_hh0  = (const float*)d_in[5];
    const float* b_ih0  = (const float*)d_in[6];
    const float* b_hh0  = (const float*)d_in[7];
    const float* W_ih1  = (const float*)d_in[8];
    const float* W_hh1  = (const float*)d_in[9];
    const float* b_ih1  = (const float*)d_in[10];
    const float* b_hh1  = (const float*)d_in[11];
    float* out = (float*)d_out;

    int smem = (4 + 2112 + 8704 + 20) * 4;
    cudaFuncSetAttribute(lstm_rec, cudaFuncAttributeMaxDynamicSharedMemorySize, smem);

    dim3 ggrid(G4v / 64, (Tv * Bv) / 128);

    // layer 0 input projection: Xg = X @ W_ih0^T + (b_ih0 + b_hh0)
    gemm_tf32<<<ggrid, 256>>>(x, 0, (long long)Tv * Iv, (long long)Iv, Iv,
                              W_ih0, b_ih0, b_hh0);
    // layer 0 recurrence (writes g_hseq)
    lstm_rec<<<GRPS * CLS, 256, smem>>>(length, W_hh0, 1);
    // layer 1 input projection: Xg = hseq @ W_ih1^T + (b_ih1 + b_hh1)
    gemm_tf32<<<ggrid, 256>>>(nullptr, 1, (long long)Hv, (long long)Bv * Hv, Hv,
                              W_ih1, b_ih1, b_hh1);
    // layer 1 recurrence (final h -> g_hfinal)
    lstm_rec<<<GRPS * CLS, 256, smem>>>(length, W_hh1, 0);
    // FC + softmax
    fc_softmax<<<Bv, 32>>>(W_fc, b_fc, out);
}

// round 8
// speedup vs baseline: 1.0140x; 1.0140x over previous
#include <cuda_runtime.h>
#include <cstdint>

#define Bv 256
#define Tv 512
#define Iv 128
#define Hv 256
#define G4v 1024
#define GRPS 16   // batch groups of 16 rows
#define MBr 16    // rows per group
#define SLC 16    // hidden slices per group (16 cols each)

// ---------------- scratch (device globals; no cudaMalloc allowed) ----------
__device__ float g_xg[(long long)Tv * Bv * G4v];    // gate preacts [t][b][4H]
__device__ float g_hseq[(long long)Tv * Bv * Hv];   // layer0 output [t][b][H]
// comb layout: [buf][group][slice][row(16)][idx(16)], idx=(c&3)*4+(c>>2)
__device__ float g_hbuf[2][GRPS][SLC][MBr][16];
__device__ float g_hfinal[Bv * Hv];
__device__ unsigned g_flags[GRPS * 32];             // one 128B line per group

// ---------------- helpers ---------------------------------------------------
__device__ __forceinline__ unsigned f2tf(float f) {
    unsigned u;
    asm("cvt.rna.tf32.f32 %0, %1;" : "=r"(u) : "f"(f));
    return u;
}
__device__ __forceinline__ void mma_tf32(float c[4], unsigned a0, unsigned a1,
                                         unsigned a2, unsigned a3,
                                         unsigned b0, unsigned b1) {
    asm volatile(
        "mma.sync.aligned.m16n8k8.row.col.f32.tf32.tf32.f32 "
        "{%0,%1,%2,%3}, {%4,%5,%6,%7}, {%8,%9}, {%0,%1,%2,%3};"
        : "+f"(c[0]), "+f"(c[1]), "+f"(c[2]), "+f"(c[3])
        : "r"(a0), "r"(a1), "r"(a2), "r"(a3), "r"(b0), "r"(b1));
}
__device__ __forceinline__ float tanhfast(float x) {
    float y;
    asm("tanh.approx.f32 %0, %1;" : "=f"(y) : "f"(x));
    return y;
}
__device__ __forceinline__ float sigm(float x) {
    return fmaf(0.5f, tanhfast(0.5f * x), 0.5f);
}

// ---------------- input-projection GEMM (tf32 mma) -------------------------
__global__ void __launch_bounds__(256) gemm_tf32(
    const float* __restrict__ A_ext, int useHseq, long long sB, long long sT, int K,
    const float* __restrict__ W, const float* __restrict__ bias1,
    const float* __restrict__ bias2)
{
    __shared__ float As[128][36];
    __shared__ float Bs[64][36];

    // reset recurrence flags for the lstm_rec kernel that follows this GEMM
    if (blockIdx.x == 0 && blockIdx.y == 0) {
        g_flags[threadIdx.x] = 0u;
        g_flags[threadIdx.x + 256] = 0u;
    }

    const float* A = useHseq ? (const float*)g_hseq : A_ext;

    int tid  = threadIdx.x;
    int lane = tid & 31, wid = tid >> 5;
    int wm = wid & 3, wn = wid >> 2;
    int mbase = wm * 32, nbase = wn * 32;
    int grp = lane >> 2, tig = lane & 3;
    int ctaN = blockIdx.x, ctaM = blockIdx.y;

    float acc[2][4][4];
#pragma unroll
    for (int a = 0; a < 2; a++)
#pragma unroll
        for (int b = 0; b < 4; b++)
#pragma unroll
            for (int c = 0; c < 4; c++) acc[a][b][c] = 0.0f;

    for (int k0 = 0; k0 < K; k0 += 32) {
#pragma unroll
        for (int i = 0; i < 4; i++) {
            int id = tid + i * 256;
            int r = id >> 3, c4 = id & 7;
            long long grow = (long long)ctaM * 128 + r;
            const float* src = A + (grow & (Bv - 1)) * sB + (grow >> 8) * sT + k0 + c4 * 4;
            float4 v = *(const float4*)src;
            As[r][c4 * 4 + 0] = __uint_as_float(f2tf(v.x));
            As[r][c4 * 4 + 1] = __uint_as_float(f2tf(v.y));
            As[r][c4 * 4 + 2] = __uint_as_float(f2tf(v.z));
            As[r][c4 * 4 + 3] = __uint_as_float(f2tf(v.w));
        }
#pragma unroll
        for (int i = 0; i < 2; i++) {
            int id = tid + i * 256;
            int r = id >> 3, c4 = id & 7;
            const float* src = W + (long long)(ctaN * 64 + r) * K + k0 + c4 * 4;
            float4 v = *(const float4*)src;
            Bs[r][c4 * 4 + 0] = __uint_as_float(f2tf(v.x));
            Bs[r][c4 * 4 + 1] = __uint_as_float(f2tf(v.y));
            Bs[r][c4 * 4 + 2] = __uint_as_float(f2tf(v.z));
            Bs[r][c4 * 4 + 3] = __uint_as_float(f2tf(v.w));
        }
        __syncthreads();

#pragma unroll
        for (int kk = 0; kk < 32; kk += 8) {
            unsigned a[2][4];
#pragma unroll
            for (int mt = 0; mt < 2; mt++) {
                int row = mbase + mt * 16 + grp;
                a[mt][0] = __float_as_uint(As[row][kk + tig]);
                a[mt][1] = __float_as_uint(As[row + 8][kk + tig]);
                a[mt][2] = __float_as_uint(As[row][kk + tig + 4]);
                a[mt][3] = __float_as_uint(As[row + 8][kk + tig + 4]);
            }
#pragma unroll
            for (int nt = 0; nt < 4; nt++) {
                int nr = nbase + nt * 8 + grp;
                unsigned b0 = __float_as_uint(Bs[nr][kk + tig]);
                unsigned b1 = __float_as_uint(Bs[nr][kk + tig + 4]);
#pragma unroll
                for (int mt = 0; mt < 2; mt++)
                    mma_tf32(acc[mt][nt], a[mt][0], a[mt][1], a[mt][2], a[mt][3], b0, b1);
            }
        }
        __syncthreads();
    }

#pragma unroll
    for (int mt = 0; mt < 2; mt++) {
#pragma unroll
        for (int nt = 0; nt < 4; nt++) {
            long long grow = (long long)ctaM * 128 + mbase + mt * 16 + grp;
            int gcol = ctaN * 64 + nbase + nt * 8 + 2 * tig;
            float bb0 = bias1[gcol] + bias2[gcol];
            float bb1 = bias1[gcol + 1] + bias2[gcol + 1];
            g_xg[grow * G4v + gcol]           = acc[mt][nt][0] + bb0;
            g_xg[grow * G4v + gcol + 1]       = acc[mt][nt][1] + bb1;
            g_xg[(grow + 8) * G4v + gcol]     = acc[mt][nt][2] + bb0;
            g_xg[(grow + 8) * G4v + gcol + 1] = acc[mt][nt][3] + bb1;
        }
    }
}

// ---------------- persistent recurrence kernel ------------------------------
// 128 CTAs; CTA (pair 0..7, hs 0..15) owns slice hs of groups {pair, pair+8}
// and alternates phases A/B each timestep. While one group's release
// propagates through L2, the other group's phase executes (latency hiding).
// Both groups share the same W_hh slice -> one Breg set.
__global__ void __launch_bounds__(256, 1) lstm_rec(
    const int* __restrict__ lengths, const float* __restrict__ W_hh, int writeSeq)
{
    __shared__ float gates[16][68];
    __shared__ int slenAB[32];
    __shared__ int pmaxAB[2];

    int tid = threadIdx.x, lane = tid & 31, wid = tid >> 5;
    int pair = blockIdx.x >> 4;       // 0..7
    int hs   = blockIdx.x & 15;       // 0..15
    int gidx[2] = { pair, pair + 8 };
    int q = wid >> 1, sub = (wid & 1) * 8;   // warp -> gate q, 8-col half
    int grp = lane >> 2, tig = lane & 3;

    // ---- W_hh fragments in registers (tf32); shared by both groups
    unsigned Breg[64];
    {
        const float* p = W_hh + (long long)(q * 256 + hs * 16 + sub + grp) * Hv + tig;
#pragma unroll
        for (int u = 0; u < 64; u++)
            Breg[u] = f2tf(__ldg(p + 4 * u));
    }

    if (tid < 32) slenAB[tid] = lengths[gidx[tid >> 4] * MBr + (tid & 15)];
    __syncthreads();
    if (tid < 2) {
        int m = 0;
        for (int i = 0; i < 16; i++) m = max(m, slenAB[tid * 16 + i]);
        pmaxAB[tid] = m;
    }
    __syncthreads();
    int maxlen[2] = { pmaxAB[0], pmaxAB[1] };
    int Tmax = max(maxlen[0], maxlen[1]);

    // epilogue mapping: thread owns (eb, col ej) of this CTA's slice
    int eb = tid >> 4, ej = tid & 15;
    int hidx = (ej & 3) * 4 + (ej >> 2);   // comb index for col ej
    int mylen[2] = { slenAB[eb], slenAB[16 + eb] };
    float hmy[2]  = { 0.0f, 0.0f };
    float cstr[2] = { 0.0f, 0.0f };

    unsigned* myflag[2] = { g_flags + gidx[0] * 32 + hs, g_flags + gidx[1] * 32 + hs };
    const unsigned* gflag[2] = { g_flags + gidx[0] * 32, g_flags + gidx[1] * 32 };

    int gc = q * 256 + hs * 16 + sub + 2 * tig;   // xg/gate global column
    float2 xgp[2][2];
#pragma unroll
    for (int ph = 0; ph < 2; ph++) {
        long long rb = (long long)(gidx[ph] * MBr + grp) * G4v;
        xgp[ph][0] = *(const float2*)(g_xg + rb + gc);
        xgp[ph][1] = *(const float2*)(g_xg + rb + 8 * G4v + gc);
    }

    for (int t = 0; t < Tmax; t++) {
        // ---- prefetch next xg for BOTH phases first (no dependencies)
        float2 xgn[2][2];
#pragma unroll
        for (int ph = 0; ph < 2; ph++) {
            if (t + 1 < maxlen[ph]) {
                long long rb = ((long long)(t + 1) * Bv + gidx[ph] * MBr + grp) * G4v;
                xgn[ph][0] = *(const float2*)(g_xg + rb + gc);
                xgn[ph][1] = *(const float2*)(g_xg + rb + 8 * G4v + gc);
            }
        }

#pragma unroll
        for (int ph = 0; ph < 2; ph++) {
            if (t < maxlen[ph]) {
                // wait: peers of this group finished step t-1
                if (t > 0) {
                    if (tid < 16) {
                        const unsigned* fp = gflag[ph] + tid;
                        unsigned v;
                        asm volatile("ld.acquire.gpu.u32 %0, [%1];" : "=r"(v) : "l"(fp));
                        while (v < (unsigned)t) {
                            __nanosleep(32);
                            asm volatile("ld.acquire.gpu.u32 %0, [%1];" : "=r"(v) : "l"(fp));
                        }
                    }
                }
                __syncthreads();

                // mma: acc = xg + h(t-1) @ W_hh_slice^T  (4 split chains)
                float acc[4][4];
                acc[0][0] = xgp[ph][0].x; acc[0][1] = xgp[ph][0].y;
                acc[0][2] = xgp[ph][1].x; acc[0][3] = xgp[ph][1].y;
#pragma unroll
                for (int ch = 1; ch < 4; ch++) {
                    acc[ch][0] = 0.0f; acc[ch][1] = 0.0f;
                    acc[ch][2] = 0.0f; acc[ch][3] = 0.0f;
                }
                if (t > 0) {
                    const float* hb = &g_hbuf[(t - 1) & 1][gidx[ph]][0][0][0];
#pragma unroll
                    for (int s = 0; s < 16; s++) {
                        const float* sb = hb + s * (MBr * 16);
                        float4 fa = *(const float4*)(sb + grp * 16 + tig * 4);
                        float4 fb = *(const float4*)(sb + (grp + 8) * 16 + tig * 4);
                        int p0 = (s & 1) * 2;
                        mma_tf32(acc[p0],
                                 __float_as_uint(fa.x), __float_as_uint(fb.x),
                                 __float_as_uint(fa.y), __float_as_uint(fb.y),
                                 Breg[4 * s], Breg[4 * s + 1]);
                        mma_tf32(acc[p0 + 1],
                                 __float_as_uint(fa.z), __float_as_uint(fb.z),
                                 __float_as_uint(fa.w), __float_as_uint(fb.w),
                                 Breg[4 * s + 2], Breg[4 * s + 3]);
                    }
                }
                xgp[ph][0] = xgn[ph][0];
                xgp[ph][1] = xgn[ph][1];

                // reduce chains -> gates SMEM (16 rows x 64 cols)
                int gcl = q * 16 + sub + 2 * tig;
                *(float2*)&gates[grp][gcl] = make_float2(
                    acc[0][0] + acc[1][0] + acc[2][0] + acc[3][0],
                    acc[0][1] + acc[1][1] + acc[2][1] + acc[3][1]);
                *(float2*)&gates[grp + 8][gcl] = make_float2(
                    acc[0][2] + acc[1][2] + acc[2][2] + acc[3][2],
                    acc[0][3] + acc[1][3] + acc[2][3] + acc[3][3]);
                __syncthreads();

                // activations + state update (c in registers)
                bool act = (t < mylen[ph]);
                if (act) {
                    float gi = gates[eb][ej];
                    float gf = gates[eb][16 + ej];
                    float gg = gates[eb][32 + ej];
                    float go = gates[eb][48 + ej];
                    float iv = sigm(gi), fv = sigm(gf);
                    float gv = tanhfast(gg), ov = sigm(go);
                    float cn = fmaf(fv, cstr[ph], iv * gv);
                    cstr[ph] = cn;
                    hmy[ph] = ov * tanhfast(cn);
                }
                // publish slice value (comb layout)
                g_hbuf[t & 1][gidx[ph]][hs][eb][hidx] = __uint_as_float(f2tf(hmy[ph]));
                __syncthreads();   // all slice stores performed CTA-wide

                // release, then off-critical-path hseq store
                if (tid == 0) {
                    unsigned nv = (unsigned)(t + 1);
                    asm volatile("st.release.gpu.u32 [%0], %1;"
                                 :: "l"(myflag[ph]), "r"(nv) : "memory");
                }
                if (writeSeq && act)
                    g_hseq[((long long)t * Bv + gidx[ph] * MBr + eb) * Hv + hs * 16 + ej]
                        = hmy[ph];
            }
        }
    }

    // publish final hidden states for FC
#pragma unroll
    for (int ph = 0; ph < 2; ph++)
        g_hfinal[(long long)(gidx[ph] * MBr + eb) * Hv + hs * 16 + ej] = hmy[ph];
}

// ---------------- final FC + softmax ----------------------------------------
__global__ void fc_softmax(const float* __restrict__ W_fc,
                           const float* __restrict__ b_fc, float* __restrict__ out)
{
    int b = blockIdx.x, lane = threadIdx.x;
    float logit[10];
#pragma unroll
    for (int c = 0; c < 10; c++) {
        float s = 0.0f;
        for (int h = lane; h < Hv; h += 32)
            s += g_hfinal[b * Hv + h] * W_fc[c * Hv + h];
#pragma unroll
        for (int o = 16; o; o >>= 1) s += __shfl_down_sync(0xffffffffu, s, o);
        logit[c] = s;
    }
    if (lane == 0) {
        float mx = -1e30f;
#pragma unroll
        for (int c = 0; c < 10; c++) {
            logit[c] += b_fc[c];
            mx = fmaxf(mx, logit[c]);
        }
        float sum = 0.0f;
#pragma unroll
        for (int c = 0; c < 10; c++) {
            logit[c] = expf(logit[c] - mx);
            sum += logit[c];
        }
        float inv = 1.0f / sum;
#pragma unroll
        for (int c = 0; c < 10; c++) out[b * 10 + c] = logit[c] * inv;
    }
}

// ---------------- host launcher ---------------------------------------------
extern "C" void kernel_launch(void* const* d_in, const int* in_sizes, int n_in,
                              void* d_out, int out_size)
{
    const float* x      = (const float*)d_in[0];
    const int*   length = (const int*)d_in[1];
    const float* W_fc   = (const float*)d_in[2];
    const float* b_fc   = (const float*)d_in[3];
    const float* W_ih0  = (const float*)d_in[4];
    const float* W_hh0  = (const float*)d_in[5];
    const float* b_ih0  = (const float*)d_in[6];
    const float* b_hh0  = (const float*)d_in[7];
    const float* W_ih1  = (const float*)d_in[8];
    const float* W_hh1  = (const float*)d_in[9];
    const float* b_ih1  = (const float*)d_in[10];
    const float* b_hh1  = (const float*)d_in[11];
    float* out = (float*)d_out;

    dim3 ggrid(G4v / 64, (Tv * Bv) / 128);

    // layer 0 input projection: Xg = X @ W_ih0^T + (b_ih0 + b_hh0)
    gemm_tf32<<<ggrid, 256>>>(x, 0, (long long)Tv * Iv, (long long)Iv, Iv,
                              W_ih0, b_ih0, b_hh0);
    // layer 0 recurrence (writes g_hseq)
    lstm_rec<<<128, 256>>>(length, W_hh0, 1);
    // layer 1 input projection: Xg = hseq @ W_ih1^T + (b_ih1 + b_hh1)
    gemm_tf32<<<ggrid, 256>>>(nullptr, 1, (long long)Hv, (long long)Bv * Hv, Hv,
                              W_ih1, b_ih1, b_hh1);
    // layer 1 recurrence (final h -> g_hfinal)
    lstm_rec<<<128, 256>>>(length, W_hh1, 0);
    // FC + softmax
    fc_softmax<<<Bv, 32>>>(W_fc, b_fc, out);
}

// round 9
// speedup vs baseline: 1.5730x; 1.5513x over previous
#include <cuda_runtime.h>
#include <cstdint>

#define Bv 256
#define Tv 512
#define Iv 128
#define Hv 256
#define G4v 1024

// ---------------- scratch (device globals; no cudaMalloc allowed) ----------
__device__ float g_xg[(long long)Tv * Bv * G4v];    // layer-0 gate preacts
// h exchange buffers, comb layout [buf][group][slice][row(32)][idx(16)],
// idx = (c&3)*4 + (c>>2) for local col c
__device__ float g_h0buf[2][8][16][32][16];
__device__ float g_h1buf[2][8][16][32][16];
__device__ float g_hfinal[Bv * Hv];
__device__ unsigned g_flags[8 * 32];                // one flag per CTA

// ---------------- helpers ---------------------------------------------------
__device__ __forceinline__ unsigned f2tf(float f) {
    unsigned u;
    asm("cvt.rna.tf32.f32 %0, %1;" : "=r"(u) : "f"(f));
    return u;
}
__device__ __forceinline__ void mma_tf32(float c[4], unsigned a0, unsigned a1,
                                         unsigned a2, unsigned a3,
                                         unsigned b0, unsigned b1) {
    asm volatile(
        "mma.sync.aligned.m16n8k8.row.col.f32.tf32.tf32.f32 "
        "{%0,%1,%2,%3}, {%4,%5,%6,%7}, {%8,%9}, {%0,%1,%2,%3};"
        : "+f"(c[0]), "+f"(c[1]), "+f"(c[2]), "+f"(c[3])
        : "r"(a0), "r"(a1), "r"(a2), "r"(a3), "r"(b0), "r"(b1));
}
__device__ __forceinline__ float tanhfast(float x) {
    float y;
    asm("tanh.approx.f32 %0, %1;" : "=f"(y) : "f"(x));
    return y;
}
__device__ __forceinline__ float sigm(float x) {
    return fmaf(0.5f, tanhfast(0.5f * x), 0.5f);
}

// ---------------- layer-0 input GEMM (tf32 mma) ----------------------------
__global__ void __launch_bounds__(256) gemm_tf32(
    const float* __restrict__ A, long long sB, long long sT, int K,
    const float* __restrict__ W, const float* __restrict__ bias1,
    const float* __restrict__ bias2)
{
    __shared__ float As[128][36];
    __shared__ float Bs[64][36];

    // reset recurrence flags for the fused kernel that follows
    if (blockIdx.x == 0 && blockIdx.y == 0)
        g_flags[threadIdx.x] = 0u;

    int tid  = threadIdx.x;
    int lane = tid & 31, wid = tid >> 5;
    int wm = wid & 3, wn = wid >> 2;
    int mbase = wm * 32, nbase = wn * 32;
    int grp = lane >> 2, tig = lane & 3;
    int ctaN = blockIdx.x, ctaM = blockIdx.y;

    float acc[2][4][4];
#pragma unroll
    for (int a = 0; a < 2; a++)
#pragma unroll
        for (int b = 0; b < 4; b++)
#pragma unroll
            for (int c = 0; c < 4; c++) acc[a][b][c] = 0.0f;

    for (int k0 = 0; k0 < K; k0 += 32) {
#pragma unroll
        for (int i = 0; i < 4; i++) {
            int id = tid + i * 256;
            int r = id >> 3, c4 = id & 7;
            long long grow = (long long)ctaM * 128 + r;
            const float* src = A + (grow & (Bv - 1)) * sB + (grow >> 8) * sT + k0 + c4 * 4;
            float4 v = *(const float4*)src;
            As[r][c4 * 4 + 0] = __uint_as_float(f2tf(v.x));
            As[r][c4 * 4 + 1] = __uint_as_float(f2tf(v.y));
            As[r][c4 * 4 + 2] = __uint_as_float(f2tf(v.z));
            As[r][c4 * 4 + 3] = __uint_as_float(f2tf(v.w));
        }
#pragma unroll
        for (int i = 0; i < 2; i++) {
            int id = tid + i * 256;
            int r = id >> 3, c4 = id & 7;
            const float* src = W + (long long)(ctaN * 64 + r) * K + k0 + c4 * 4;
            float4 v = *(const float4*)src;
            Bs[r][c4 * 4 + 0] = __uint_as_float(f2tf(v.x));
            Bs[r][c4 * 4 + 1] = __uint_as_float(f2tf(v.y));
            Bs[r][c4 * 4 + 2] = __uint_as_float(f2tf(v.z));
            Bs[r][c4 * 4 + 3] = __uint_as_float(f2tf(v.w));
        }
        __syncthreads();

#pragma unroll
        for (int kk = 0; kk < 32; kk += 8) {
            unsigned a[2][4];
#pragma unroll
            for (int mt = 0; mt < 2; mt++) {
                int row = mbase + mt * 16 + grp;
                a[mt][0] = __float_as_uint(As[row][kk + tig]);
                a[mt][1] = __float_as_uint(As[row + 8][kk + tig]);
                a[mt][2] = __float_as_uint(As[row][kk + tig + 4]);
                a[mt][3] = __float_as_uint(As[row + 8][kk + tig + 4]);
            }
#pragma unroll
            for (int nt = 0; nt < 4; nt++) {
                int nr = nbase + nt * 8 + grp;
                unsigned b0 = __float_as_uint(Bs[nr][kk + tig]);
                unsigned b1 = __float_as_uint(Bs[nr][kk + tig + 4]);
#pragma unroll
                for (int mt = 0; mt < 2; mt++)
                    mma_tf32(acc[mt][nt], a[mt][0], a[mt][1], a[mt][2], a[mt][3], b0, b1);
            }
        }
        __syncthreads();
    }

#pragma unroll
    for (int mt = 0; mt < 2; mt++) {
#pragma unroll
        for (int nt = 0; nt < 4; nt++) {
            long long grow = (long long)ctaM * 128 + mbase + mt * 16 + grp;
            int gcol = ctaN * 64 + nbase + nt * 8 + 2 * tig;
            float bb0 = bias1[gcol] + bias2[gcol];
            float bb1 = bias1[gcol + 1] + bias2[gcol + 1];
            g_xg[grow * G4v + gcol]           = acc[mt][nt][0] + bb0;
            g_xg[grow * G4v + gcol + 1]       = acc[mt][nt][1] + bb1;
            g_xg[(grow + 8) * G4v + gcol]     = acc[mt][nt][2] + bb0;
            g_xg[(grow + 8) * G4v + gcol + 1] = acc[mt][nt][3] + bb1;
        }
    }
}

// ---------------- fused 2-layer recurrence (wavefront pipeline) -------------
// 128 CTAs: bt (8 groups of 32 batch rows) x hs (16 H-slices of 16 cols).
// Round t: layer-0 step t AND layer-1 step t-1 (513 rounds total).
// Weights in SMEM comb layout; ONE wait + ONE release per round.
__global__ void __launch_bounds__(256, 1) lstm_fused(
    const int* __restrict__ lengths,
    const float* __restrict__ W_hh0,
    const float* __restrict__ W_ih1, const float* __restrict__ W_hh1,
    const float* __restrict__ b_ih1, const float* __restrict__ b_hh1)
{
    extern __shared__ float sm[];
    float* W0s = sm;                                     // 64*4 segs * 68
    float* W1s = sm + 17408;                             // 64*4 segs * 132
    float (*gates0)[68] = (float(*)[68])(sm + 51200);    // 32 x 68
    float (*gates1)[68] = (float(*)[68])(sm + 53376);    // 32 x 68
    int* slen = (int*)(sm + 55552);
    int* pmax = slen + 32;

    int tid = threadIdx.x, lane = tid & 31, wid = tid >> 5;
    int bt = blockIdx.x & 7;
    int hs = blockIdx.x >> 3;
    int wm = wid & 1, wn = wid >> 1;     // 2(M) x 4(N=gate) warps
    int grp = lane >> 2, tig = lane & 3;
    int arow0 = wm * 16 + grp;

    // ---- stage weights into SMEM (tf32, comb layout)
    for (int idx = tid; idx < 64 * 256; idx += 256) {
        int rr = idx >> 8, k = idx & 255;
        int R = (rr >> 4) * 256 + hs * 16 + (rr & 15);
        W0s[(rr * 4 + (k & 3)) * 68 + (k >> 2)] =
            __uint_as_float(f2tf(W_hh0[R * 256 + k]));
    }
    for (int idx = tid; idx < 64 * 512; idx += 256) {
        int rr = idx >> 9, k = idx & 511;
        int R = (rr >> 4) * 256 + hs * 16 + (rr & 15);
        float v = (k < 256) ? W_ih1[R * 256 + k] : W_hh1[R * 256 + (k - 256)];
        W1s[(rr * 4 + (k & 3)) * 132 + (k >> 2)] = __uint_as_float(f2tf(v));
    }
    if (tid < 32) slen[tid] = lengths[bt * 32 + tid];
    __syncthreads();
    if (tid == 0) {
        int m = 0;
        for (int i = 0; i < 32; i++) m = max(m, slen[i]);
        pmax[0] = m;
    }
    __syncthreads();
    int maxlen = pmax[0];

    unsigned* myflag = g_flags + bt * 32 + hs;
    const unsigned* gflag = g_flags + bt * 32;

    // per-warp B segment bases
    int segB0[2], segB1[2];
#pragma unroll
    for (int nt = 0; nt < 2; nt++) {
        int rr = wn * 16 + nt * 8 + grp;
        segB0[nt] = (rr * 4 + tig) * 68;
        segB1[nt] = (rr * 4 + tig) * 132;
    }
    // layer-1 bias for this thread's gate columns
    float bs[2][2];
#pragma unroll
    for (int nt = 0; nt < 2; nt++) {
        int col = wn * 256 + hs * 16 + nt * 8 + 2 * tig;
        bs[nt][0] = b_ih1[col] + b_hh1[col];
        bs[nt][1] = b_ih1[col + 1] + b_hh1[col + 1];
    }

    // epilogue mapping: thread owns (eb, cols ej, ej+1)
    int eb = tid >> 3, ej = (tid & 7) * 2;
    int hidx0 = (ej & 3) * 4 + (ej >> 2);
    int hidx1 = ((ej + 1) & 3) * 4 + ((ej + 1) >> 2);
    int mylen = slen[eb];
    float2 hmy0 = make_float2(0.f, 0.f), hmy1 = make_float2(0.f, 0.f);
    float2 c0 = make_float2(0.f, 0.f), c1 = make_float2(0.f, 0.f);

    // xg prefetch (mma accumulator layout)
    int gc = wn * 256 + hs * 16 + 2 * tig;
    float2 xgp[2][2];
    {
        long long rb = (long long)(bt * 32 + arow0) * G4v;
#pragma unroll
        for (int nt = 0; nt < 2; nt++) {
            xgp[nt][0] = *(const float2*)(g_xg + rb + gc + nt * 8);
            xgp[nt][1] = *(const float2*)(g_xg + rb + 8 * G4v + gc + nt * 8);
        }
    }

    for (int t = 0; t <= maxlen; t++) {
        // ---- 1. prefetch xg(t+1) (no dependencies)
        float2 xgn[2][2];
        if (t + 1 < maxlen) {
            long long rb = ((long long)(t + 1) * Bv + bt * 32 + arow0) * G4v;
#pragma unroll
            for (int nt = 0; nt < 2; nt++) {
                xgn[nt][0] = *(const float2*)(g_xg + rb + gc + nt * 8);
                xgn[nt][1] = *(const float2*)(g_xg + rb + 8 * G4v + gc + nt * 8);
            }
        }

        // ---- 2. single wait: all peers completed round t-1
        if (t > 0) {
            if (tid < 16) {
                const unsigned* fp = gflag + tid;
                unsigned v;
                asm volatile("ld.acquire.gpu.u32 %0, [%1];" : "=r"(v) : "l"(fp));
                while (v < (unsigned)t) {
                    __nanosleep(32);
                    asm volatile("ld.acquire.gpu.u32 %0, [%1];" : "=r"(v) : "l"(fp));
                }
            }
        }
        __syncthreads();

        // ---- 3. mma phase
        float acc0[2][2][4];     // L0: chain x ntile x frag
        float acc1[4][2][4];     // L1: 4 chains
#pragma unroll
        for (int nt = 0; nt < 2; nt++) {
            acc0[0][nt][0] = xgp[nt][0].x; acc0[0][nt][1] = xgp[nt][0].y;
            acc0[0][nt][2] = xgp[nt][1].x; acc0[0][nt][3] = xgp[nt][1].y;
            acc0[1][nt][0] = 0.f; acc0[1][nt][1] = 0.f;
            acc0[1][nt][2] = 0.f; acc0[1][nt][3] = 0.f;
            acc1[0][nt][0] = bs[nt][0]; acc1[0][nt][1] = bs[nt][1];
            acc1[0][nt][2] = bs[nt][0]; acc1[0][nt][3] = bs[nt][1];
#pragma unroll
            for (int ch = 1; ch < 4; ch++) {
                acc1[ch][nt][0] = 0.f; acc1[ch][nt][1] = 0.f;
                acc1[ch][nt][2] = 0.f; acc1[ch][nt][3] = 0.f;
            }
        }

        if (t > 0) {
            // h0(t-1) fragments feed BOTH L0 (W0s) and L1 first half (W1s)
            const float* hb = &g_h0buf[(t - 1) & 1][bt][0][0][0];
#pragma unroll
            for (int s = 0; s < 16; s++) {
                const float* sb = hb + s * 512;
                float4 fa = *(const float4*)(sb + arow0 * 16 + tig * 4);
                float4 fb = *(const float4*)(sb + (arow0 + 8) * 16 + tig * 4);
                unsigned ax = __float_as_uint(fa.x), bx = __float_as_uint(fb.x);
                unsigned ay = __float_as_uint(fa.y), by = __float_as_uint(fb.y);
                unsigned az = __float_as_uint(fa.z), bz = __float_as_uint(fb.z);
                unsigned aw = __float_as_uint(fa.w), bw = __float_as_uint(fb.w);
                int c2 = 2 * (s & 1);
#pragma unroll
                for (int nt = 0; nt < 2; nt++) {
                    float4 p0 = *(const float4*)&W0s[segB0[nt] + 4 * s];
                    mma_tf32(acc0[0][nt], ax, bx, ay, by,
                             __float_as_uint(p0.x), __float_as_uint(p0.y));
                    mma_tf32(acc0[1][nt], az, bz, aw, bw,
                             __float_as_uint(p0.z), __float_as_uint(p0.w));
                    float4 p1 = *(const float4*)&W1s[segB1[nt] + 4 * s];
                    mma_tf32(acc1[c2][nt], ax, bx, ay, by,
                             __float_as_uint(p1.x), __float_as_uint(p1.y));
                    mma_tf32(acc1[c2 + 1][nt], az, bz, aw, bw,
                             __float_as_uint(p1.z), __float_as_uint(p1.w));
                }
            }
        }
        if (t > 1) {
            // h1(t-2) fragments against W_hh1 (upper half of W1s)
            const float* hb = &g_h1buf[t & 1][bt][0][0][0];
#pragma unroll
            for (int s = 0; s < 16; s++) {
                const float* sb = hb + s * 512;
                float4 fa = *(const float4*)(sb + arow0 * 16 + tig * 4);
                float4 fb = *(const float4*)(sb + (arow0 + 8) * 16 + tig * 4);
                int c2 = 2 * (s & 1);
#pragma unroll
                for (int nt = 0; nt < 2; nt++) {
                    float4 p1 = *(const float4*)&W1s[segB1[nt] + 64 + 4 * s];
                    mma_tf32(acc1[c2][nt],
                             __float_as_uint(fa.x), __float_as_uint(fb.x),
                             __float_as_uint(fa.y), __float_as_uint(fb.y),
                             __float_as_uint(p1.x), __float_as_uint(p1.y));
                    mma_tf32(acc1[c2 + 1][nt],
                             __float_as_uint(fa.z), __float_as_uint(fb.z),
                             __float_as_uint(fa.w), __float_as_uint(fb.w),
                             __float_as_uint(p1.z), __float_as_uint(p1.w));
                }
            }
        }
        xgp[0][0] = xgn[0][0]; xgp[0][1] = xgn[0][1];
        xgp[1][0] = xgn[1][0]; xgp[1][1] = xgn[1][1];

        // ---- 4. write gate preacts (separate buffers, one sync)
#pragma unroll
        for (int nt = 0; nt < 2; nt++) {
            int gcl = wn * 16 + nt * 8 + 2 * tig;
            if (t < maxlen) {
                *(float2*)&gates0[arow0][gcl] = make_float2(
                    acc0[0][nt][0] + acc0[1][nt][0],
                    acc0[0][nt][1] + acc0[1][nt][1]);
                *(float2*)&gates0[arow0 + 8][gcl] = make_float2(
                    acc0[0][nt][2] + acc0[1][nt][2],
                    acc0[0][nt][3] + acc0[1][nt][3]);
            }
            if (t >= 1) {
                *(float2*)&gates1[arow0][gcl] = make_float2(
                    acc1[0][nt][0] + acc1[1][nt][0] + acc1[2][nt][0] + acc1[3][nt][0],
                    acc1[0][nt][1] + acc1[1][nt][1] + acc1[2][nt][1] + acc1[3][nt][1]);
                *(float2*)&gates1[arow0 + 8][gcl] = make_float2(
                    acc1[0][nt][2] + acc1[1][nt][2] + acc1[2][nt][2] + acc1[3][nt][2],
                    acc1[0][nt][3] + acc1[1][nt][3] + acc1[2][nt][3] + acc1[3][nt][3]);
            }
        }
        __syncthreads();

        // ---- 5. epilogues
        if (t < maxlen) {
            bool act = (t < mylen);
            if (act) {
                float2 gi = *(const float2*)&gates0[eb][ej];
                float2 gf = *(const float2*)&gates0[eb][16 + ej];
                float2 gg = *(const float2*)&gates0[eb][32 + ej];
                float2 go = *(const float2*)&gates0[eb][48 + ej];
                float i0 = sigm(gi.x), i1 = sigm(gi.y);
                float f0 = sigm(gf.x), f1 = sigm(gf.y);
                float g0 = tanhfast(gg.x), g1 = tanhfast(gg.y);
                float o0 = sigm(go.x), o1 = sigm(go.y);
                float cn0 = fmaf(f0, c0.x, i0 * g0);
                float cn1 = fmaf(f1, c0.y, i1 * g1);
                c0 = make_float2(cn0, cn1);
                hmy0 = make_float2(o0 * tanhfast(cn0), o1 * tanhfast(cn1));
            }
            float* d = &g_h0buf[t & 1][bt][hs][eb][0];
            d[hidx0] = __uint_as_float(f2tf(hmy0.x));
            d[hidx1] = __uint_as_float(f2tf(hmy0.y));
        }
        if (t >= 1) {
            bool act = (t - 1 < mylen);
            if (act) {
                float2 gi = *(const float2*)&gates1[eb][ej];
                float2 gf = *(const float2*)&gates1[eb][16 + ej];
                float2 gg = *(const float2*)&gates1[eb][32 + ej];
                float2 go = *(const float2*)&gates1[eb][48 + ej];
                float i0 = sigm(gi.x), i1 = sigm(gi.y);
                float f0 = sigm(gf.x), f1 = sigm(gf.y);
                float g0 = tanhfast(gg.x), g1 = tanhfast(gg.y);
                float o0 = sigm(go.x), o1 = sigm(go.y);
                float cn0 = fmaf(f0, c1.x, i0 * g0);
                float cn1 = fmaf(f1, c1.y, i1 * g1);
                c1 = make_float2(cn0, cn1);
                hmy1 = make_float2(o0 * tanhfast(cn0), o1 * tanhfast(cn1));
            }
            float* d = &g_h1buf[(t - 1) & 1][bt][hs][eb][0];
            d[hidx0] = __uint_as_float(f2tf(hmy1.x));
            d[hidx1] = __uint_as_float(f2tf(hmy1.y));
        }
        __syncthreads();

        // ---- 6. single release: round t fully done
        if (tid == 0) {
            unsigned nv = (unsigned)(t + 1);
            asm volatile("st.release.gpu.u32 [%0], %1;" :: "l"(myflag), "r"(nv) : "memory");
        }
    }

    // publish final layer-1 hidden state for FC
    float* d = g_hfinal + (long long)(bt * 32 + eb) * Hv + hs * 16;
    d[ej] = hmy1.x;
    d[ej + 1] = hmy1.y;
}

// ---------------- final FC + softmax ----------------------------------------
__global__ void fc_softmax(const float* __restrict__ W_fc,
                           const float* __restrict__ b_fc, float* __restrict__ out)
{
    int b = blockIdx.x, lane = threadIdx.x;
    float logit[10];
#pragma unroll
    for (int c = 0; c < 10; c++) {
        float s = 0.0f;
        for (int h = lane; h < Hv; h += 32)
            s += g_hfinal[b * Hv + h] * W_fc[c * Hv + h];
#pragma unroll
        for (int o = 16; o; o >>= 1) s += __shfl_down_sync(0xffffffffu, s, o);
        logit[c] = s;
    }
    if (lane == 0) {
        float mx = -1e30f;
#pragma unroll
        for (int c = 0; c < 10; c++) {
            logit[c] += b_fc[c];
            mx = fmaxf(mx, logit[c]);
        }
        float sum = 0.0f;
#pragma unroll
        for (int c = 0; c < 10; c++) {
            logit[c] = expf(logit[c] - mx);
            sum += logit[c];
        }
        float inv = 1.0f / sum;
#pragma unroll
        for (int c = 0; c < 10; c++) out[b * 10 + c] = logit[c] * inv;
    }
}

// ---------------- host launcher ---------------------------------------------
extern "C" void kernel_launch(void* const* d_in, const int* in_sizes, int n_in,
                              void* d_out, int out_size)
{
    const float* x      = (const float*)d_in[0];
    const int*   length = (const int*)d_in[1];
    const float* W_fc   = (const float*)d_in[2];
    const float* b_fc   = (const float*)d_in[3];
    const float* W_ih0  = (const float*)d_in[4];
    const float* W_hh0  = (const float*)d_in[5];
    const float* b_ih0  = (const float*)d_in[6];
    const float* b_hh0  = (const float*)d_in[7];
    const float* W_ih1  = (const float*)d_in[8];
    const float* W_hh1  = (const float*)d_in[9];
    const float* b_ih1  = (const float*)d_in[10];
    const float* b_hh1  = (const float*)d_in[11];
    float* out = (float*)d_out;

    int smem = (17408 + 33792 + 2176 + 2176 + 40) * 4;  // 222,368 B
    cudaFuncSetAttribute(lstm_fused, cudaFuncAttributeMaxDynamicSharedMemorySize, smem);

    dim3 ggrid(G4v / 64, (Tv * Bv) / 128);

    // layer 0 input projection: Xg = X @ W_ih0^T + (b_ih0 + b_hh0)
    gemm_tf32<<<ggrid, 256>>>(x, (long long)Tv * Iv, (long long)Iv, Iv,
                              W_ih0, b_ih0, b_hh0);
    // fused 2-layer recurrence (wavefront): 513 rounds
    lstm_fused<<<128, 256, smem>>>(length, W_hh0, W_ih1, W_hh1, b_ih1, b_hh1);
    // FC + softmax
    fc_softmax<<<Bv, 32>>>(W_fc, b_fc, out);
}

// round 10
// speedup vs baseline: 2.2193x; 1.4109x over previous
#include <cuda_runtime.h>
#include <cstdint>

#define Bv 256
#define Tv 512
#define Iv 128
#define Hv 256
#define G4v 1024

// ---------------- scratch (device globals; no cudaMalloc allowed) ----------
__device__ float g_xg[(long long)Tv * Bv * G4v];    // layer-0 gate preacts (f32)
// h exchange buffers, bf16x2 pairs: [buf][group][slice][row(32)][pp(8)]
// pair p (cols 2p,2p+1) stored at pp=(p&3)*2+(p>>2)  (comb for LDS.64 frags)
__device__ __align__(16) unsigned g_h0buf[2][8][16][32][8];
__device__ __align__(16) unsigned g_h1buf[2][8][16][32][8];
__device__ float g_hfinal[Bv * Hv];
__device__ unsigned g_flags[8 * 32];                // one flag per CTA

// ---------------- helpers ---------------------------------------------------
__device__ __forceinline__ unsigned f2tf(float f) {
    unsigned u;
    asm("cvt.rna.tf32.f32 %0, %1;" : "=r"(u) : "f"(f));
    return u;
}
__device__ __forceinline__ unsigned packbf(float lo, float hi) {
    unsigned r;
    asm("cvt.rn.bf16x2.f32 %0, %1, %2;" : "=r"(r) : "f"(hi), "f"(lo));
    return r;
}
__device__ __forceinline__ void mma_tf32(float c[4], unsigned a0, unsigned a1,
                                         unsigned a2, unsigned a3,
                                         unsigned b0, unsigned b1) {
    asm volatile(
        "mma.sync.aligned.m16n8k8.row.col.f32.tf32.tf32.f32 "
        "{%0,%1,%2,%3}, {%4,%5,%6,%7}, {%8,%9}, {%0,%1,%2,%3};"
        : "+f"(c[0]), "+f"(c[1]), "+f"(c[2]), "+f"(c[3])
        : "r"(a0), "r"(a1), "r"(a2), "r"(a3), "r"(b0), "r"(b1));
}
__device__ __forceinline__ void mma_bf16(float c[4], unsigned a0, unsigned a1,
                                         unsigned a2, unsigned a3,
                                         unsigned b0, unsigned b1) {
    asm volatile(
        "mma.sync.aligned.m16n8k16.row.col.f32.bf16.bf16.f32 "
        "{%0,%1,%2,%3}, {%4,%5,%6,%7}, {%8,%9}, {%0,%1,%2,%3};"
        : "+f"(c[0]), "+f"(c[1]), "+f"(c[2]), "+f"(c[3])
        : "r"(a0), "r"(a1), "r"(a2), "r"(a3), "r"(b0), "r"(b1));
}
__device__ __forceinline__ float tanhfast(float x) {
    float y;
    asm("tanh.approx.f32 %0, %1;" : "=f"(y) : "f"(x));
    return y;
}
__device__ __forceinline__ float sigm(float x) {
    return fmaf(0.5f, tanhfast(0.5f * x), 0.5f);
}

// ---------------- layer-0 input GEMM (tf32 mma, unchanged) -----------------
__global__ void __launch_bounds__(256) gemm_tf32(
    const float* __restrict__ A, long long sB, long long sT, int K,
    const float* __restrict__ W, const float* __restrict__ bias1,
    const float* __restrict__ bias2)
{
    __shared__ float As[128][36];
    __shared__ float Bs[64][36];

    if (blockIdx.x == 0 && blockIdx.y == 0)
        g_flags[threadIdx.x] = 0u;

    int tid  = threadIdx.x;
    int lane = tid & 31, wid = tid >> 5;
    int wm = wid & 3, wn = wid >> 2;
    int mbase = wm * 32, nbase = wn * 32;
    int grp = lane >> 2, tig = lane & 3;
    int ctaN = blockIdx.x, ctaM = blockIdx.y;

    float acc[2][4][4];
#pragma unroll
    for (int a = 0; a < 2; a++)
#pragma unroll
        for (int b = 0; b < 4; b++)
#pragma unroll
            for (int c = 0; c < 4; c++) acc[a][b][c] = 0.0f;

    for (int k0 = 0; k0 < K; k0 += 32) {
#pragma unroll
        for (int i = 0; i < 4; i++) {
            int id = tid + i * 256;
            int r = id >> 3, c4 = id & 7;
            long long grow = (long long)ctaM * 128 + r;
            const float* src = A + (grow & (Bv - 1)) * sB + (grow >> 8) * sT + k0 + c4 * 4;
            float4 v = *(const float4*)src;
            As[r][c4 * 4 + 0] = __uint_as_float(f2tf(v.x));
            As[r][c4 * 4 + 1] = __uint_as_float(f2tf(v.y));
            As[r][c4 * 4 + 2] = __uint_as_float(f2tf(v.z));
            As[r][c4 * 4 + 3] = __uint_as_float(f2tf(v.w));
        }
#pragma unroll
        for (int i = 0; i < 2; i++) {
            int id = tid + i * 256;
            int r = id >> 3, c4 = id & 7;
            const float* src = W + (long long)(ctaN * 64 + r) * K + k0 + c4 * 4;
            float4 v = *(const float4*)src;
            Bs[r][c4 * 4 + 0] = __uint_as_float(f2tf(v.x));
            Bs[r][c4 * 4 + 1] = __uint_as_float(f2tf(v.y));
            Bs[r][c4 * 4 + 2] = __uint_as_float(f2tf(v.z));
            Bs[r][c4 * 4 + 3] = __uint_as_float(f2tf(v.w));
        }
        __syncthreads();

#pragma unroll
        for (int kk = 0; kk < 32; kk += 8) {
            unsigned a[2][4];
#pragma unroll
            for (int mt = 0; mt < 2; mt++) {
                int row = mbase + mt * 16 + grp;
                a[mt][0] = __float_as_uint(As[row][kk + tig]);
                a[mt][1] = __float_as_uint(As[row + 8][kk + tig]);
                a[mt][2] = __float_as_uint(As[row][kk + tig + 4]);
                a[mt][3] = __float_as_uint(As[row + 8][kk + tig + 4]);
            }
#pragma unroll
            for (int nt = 0; nt < 4; nt++) {
                int nr = nbase + nt * 8 + grp;
                unsigned b0 = __float_as_uint(Bs[nr][kk + tig]);
                unsigned b1 = __float_as_uint(Bs[nr][kk + tig + 4]);
#pragma unroll
                for (int mt = 0; mt < 2; mt++)
                    mma_tf32(acc[mt][nt], a[mt][0], a[mt][1], a[mt][2], a[mt][3], b0, b1);
            }
        }
        __syncthreads();
    }

#pragma unroll
    for (int mt = 0; mt < 2; mt++) {
#pragma unroll
        for (int nt = 0; nt < 4; nt++) {
            long long grow = (long long)ctaM * 128 + mbase + mt * 16 + grp;
            int gcol = ctaN * 64 + nbase + nt * 8 + 2 * tig;
            float bb0 = bias1[gcol] + bias2[gcol];
            float bb1 = bias1[gcol + 1] + bias2[gcol + 1];
            g_xg[grow * G4v + gcol]           = acc[mt][nt][0] + bb0;
            g_xg[grow * G4v + gcol + 1]       = acc[mt][nt][1] + bb1;
            g_xg[(grow + 8) * G4v + gcol]     = acc[mt][nt][2] + bb0;
            g_xg[(grow + 8) * G4v + gcol + 1] = acc[mt][nt][3] + bb1;
        }
    }
}

// ---------------- fused 2-layer recurrence (bf16 wavefront) ------------------
// 128 CTAs: bt (8 groups of 32 batch rows) x hs (16 H-slices of 16 cols).
// Round t: L0 step t + L1 step t-1. bf16 m16n8k16 mma; h staged to SMEM once
// per round (kills L2 fragment duplication); W_hh0 fragments in registers.
// SMEM (u32): W1s 16384 | Hs0 4096 | Hs1 4096 | gates0 2176 | gates1 2176 | misc
__global__ void __launch_bounds__(256, 1) lstm_fused(
    const int* __restrict__ lengths,
    const float* __restrict__ W_hh0,
    const float* __restrict__ W_ih1, const float* __restrict__ W_hh1,
    const float* __restrict__ b_ih1, const float* __restrict__ b_hh1)
{
    extern __shared__ unsigned smu[];
    unsigned* W1s = smu;                   // [s32][ntile8][n8][pp8]
    unsigned* Hs0 = smu + 16384;           // [s16][row32][pp8]
    unsigned* Hs1 = smu + 20480;
    float (*gates0)[68] = (float(*)[68])(smu + 24576);
    float (*gates1)[68] = (float(*)[68])(smu + 26752);
    int* slen = (int*)(smu + 28928);
    int* pmax = (int*)(smu + 28960);

    int tid = threadIdx.x, lane = tid & 31, wid = tid >> 5;
    int bt = blockIdx.x & 7;
    int hs = blockIdx.x >> 3;
    int wm = wid & 1, wn = wid >> 1;       // 2(M) x 4(N=gate) warps
    int grp = lane >> 2, tig = lane & 3;
    int arow0 = wm * 16 + grp;

    // ---- W_hh0 B-fragments in registers (bf16 pairs)
    unsigned Wr0[2][16][2];
#pragma unroll
    for (int nt = 0; nt < 2; nt++) {
        int n = wn * 256 + hs * 16 + nt * 8 + grp;
        const float* p = W_hh0 + (long long)n * Hv;
#pragma unroll
        for (int s = 0; s < 16; s++) {
            Wr0[nt][s][0] = packbf(__ldg(p + s * 16 + 2 * tig),
                                   __ldg(p + s * 16 + 2 * tig + 1));
            Wr0[nt][s][1] = packbf(__ldg(p + s * 16 + 2 * tig + 8),
                                   __ldg(p + s * 16 + 2 * tig + 9));
        }
    }

    // ---- stage W1 = [W_ih1 | W_hh1] into SMEM (bf16 pairs, frag layout)
    for (int i = tid; i < 16384; i += 256) {
        int s = i >> 9, tp = (i >> 6) & 7, n = (i >> 3) & 7, pp = i & 7;
        int p = (pp >> 1) + ((pp & 1) << 2);
        int R = (tp >> 1) * 256 + hs * 16 + ((tp & 1) << 3) + n;
        int k = s * 16 + 2 * p;
        float lo, hi;
        if (k < 256) { lo = W_ih1[R * 256 + k]; hi = W_ih1[R * 256 + k + 1]; }
        else         { lo = W_hh1[R * 256 + k - 256]; hi = W_hh1[R * 256 + k - 255]; }
        W1s[i] = packbf(lo, hi);
    }
    if (tid < 32) slen[tid] = lengths[bt * 32 + tid];
    __syncthreads();
    if (tid == 0) {
        int m = 0;
        for (int i = 0; i < 32; i++) m = max(m, slen[i]);
        pmax[0] = m;
    }
    __syncthreads();
    int maxlen = pmax[0];

    unsigned* myflag = g_flags + bt * 32 + hs;
    const unsigned* gflag = g_flags + bt * 32;

    // L1 bias (accumulator-mapped)
    float bs[2][2];
#pragma unroll
    for (int nt = 0; nt < 2; nt++) {
        int col = wn * 256 + hs * 16 + nt * 8 + 2 * tig;
        bs[nt][0] = b_ih1[col] + b_hh1[col];
        bs[nt][1] = b_ih1[col + 1] + b_hh1[col + 1];
    }

    // epilogue mapping: thread owns (eb, cols 2p8, 2p8+1)
    int eb = tid >> 3, p8 = tid & 7, ej = 2 * p8;
    int pp8 = (p8 & 3) * 2 + (p8 >> 2);
    int mylen = slen[eb];
    float2 hmy0 = make_float2(0.f, 0.f), hmy1 = make_float2(0.f, 0.f);
    float2 c0 = make_float2(0.f, 0.f), c1 = make_float2(0.f, 0.f);

    int gc = wn * 256 + hs * 16 + 2 * tig;
    float2 xgp[2][2];
    {
        long long rb = (long long)(bt * 32 + arow0) * G4v;
#pragma unroll
        for (int nt = 0; nt < 2; nt++) {
            xgp[nt][0] = *(const float2*)(g_xg + rb + gc + nt * 8);
            xgp[nt][1] = *(const float2*)(g_xg + rb + 8 * G4v + gc + nt * 8);
        }
    }

    for (int t = 0; t <= maxlen; t++) {
        // ---- 1. prefetch xg(t+1)
        float2 xgn[2][2];
        if (t + 1 < maxlen) {
            long long rb = ((long long)(t + 1) * Bv + bt * 32 + arow0) * G4v;
#pragma unroll
            for (int nt = 0; nt < 2; nt++) {
                xgn[nt][0] = *(const float2*)(g_xg + rb + gc + nt * 8);
                xgn[nt][1] = *(const float2*)(g_xg + rb + 8 * G4v + gc + nt * 8);
            }
        }

        // ---- 2. wait: all 16 peers completed round t-1
        if (t > 0) {
            if (tid < 16) {
                const unsigned* fp = gflag + tid;
                unsigned v;
                do {
                    asm volatile("ld.acquire.gpu.u32 %0, [%1];" : "=r"(v) : "l"(fp));
                } while (v < (unsigned)t);
            }
        }
        __syncthreads();

        // ---- 3. stage h tiles into SMEM (coalesced, each byte once)
        if (t > 0) {
            const uint4* s4 = (const uint4*)&g_h0buf[(t - 1) & 1][bt][0][0][0];
            uint4* d4 = (uint4*)Hs0;
#pragma unroll
            for (int i = 0; i < 4; i++) d4[tid + i * 256] = s4[tid + i * 256];
        }
        if (t > 1) {
            const uint4* s4 = (const uint4*)&g_h1buf[t & 1][bt][0][0][0];
            uint4* d4 = (uint4*)Hs1;
#pragma unroll
            for (int i = 0; i < 4; i++) d4[tid + i * 256] = s4[tid + i * 256];
        }
        __syncthreads();

        // ---- 4. mma phase (bf16 k16; split accumulator chains)
        float acc0[2][2][4];
        float acc1[4][2][4];
#pragma unroll
        for (int nt = 0; nt < 2; nt++) {
            acc0[0][nt][0] = xgp[nt][0].x; acc0[0][nt][1] = xgp[nt][0].y;
            acc0[0][nt][2] = xgp[nt][1].x; acc0[0][nt][3] = xgp[nt][1].y;
            acc0[1][nt][0] = 0.f; acc0[1][nt][1] = 0.f;
            acc0[1][nt][2] = 0.f; acc0[1][nt][3] = 0.f;
            acc1[0][nt][0] = bs[nt][0]; acc1[0][nt][1] = bs[nt][1];
            acc1[0][nt][2] = bs[nt][0]; acc1[0][nt][3] = bs[nt][1];
#pragma unroll
            for (int ch = 1; ch < 4; ch++) {
                acc1[ch][nt][0] = 0.f; acc1[ch][nt][1] = 0.f;
                acc1[ch][nt][2] = 0.f; acc1[ch][nt][3] = 0.f;
            }
        }

        if (t > 0) {
#pragma unroll
            for (int s = 0; s < 16; s++) {
                uint2 lo = *(const uint2*)&Hs0[s * 256 + arow0 * 8 + 2 * tig];
                uint2 hi = *(const uint2*)&Hs0[s * 256 + (arow0 + 8) * 8 + 2 * tig];
#pragma unroll
                for (int nt = 0; nt < 2; nt++) {
                    mma_bf16(acc0[s & 1][nt], lo.x, hi.x, lo.y, hi.y,
                             Wr0[nt][s][0], Wr0[nt][s][1]);
                    uint2 wb = *(const uint2*)
                        &W1s[((s * 8 + wn * 2 + nt) * 8 + grp) * 8 + 2 * tig];
                    mma_bf16(acc1[s & 1][nt], lo.x, hi.x, lo.y, hi.y, wb.x, wb.y);
                }
            }
        }
        if (t > 1) {
#pragma unroll
            for (int s = 0; s < 16; s++) {
                uint2 lo = *(const uint2*)&Hs1[s * 256 + arow0 * 8 + 2 * tig];
                uint2 hi = *(const uint2*)&Hs1[s * 256 + (arow0 + 8) * 8 + 2 * tig];
#pragma unroll
                for (int nt = 0; nt < 2; nt++) {
                    uint2 wb = *(const uint2*)
                        &W1s[(((16 + s) * 8 + wn * 2 + nt) * 8 + grp) * 8 + 2 * tig];
                    mma_bf16(acc1[2 + (s & 1)][nt], lo.x, hi.x, lo.y, hi.y, wb.x, wb.y);
                }
            }
        }
        xgp[0][0] = xgn[0][0]; xgp[0][1] = xgn[0][1];
        xgp[1][0] = xgn[1][0]; xgp[1][1] = xgn[1][1];

        // ---- 5. write gate preacts
#pragma unroll
        for (int nt = 0; nt < 2; nt++) {
            int gcl = wn * 16 + nt * 8 + 2 * tig;
            if (t < maxlen) {
                *(float2*)&gates0[arow0][gcl] = make_float2(
                    acc0[0][nt][0] + acc0[1][nt][0],
                    acc0[0][nt][1] + acc0[1][nt][1]);
                *(float2*)&gates0[arow0 + 8][gcl] = make_float2(
                    acc0[0][nt][2] + acc0[1][nt][2],
                    acc0[0][nt][3] + acc0[1][nt][3]);
            }
            if (t >= 1) {
                *(float2*)&gates1[arow0][gcl] = make_float2(
                    acc1[0][nt][0] + acc1[1][nt][0] + acc1[2][nt][0] + acc1[3][nt][0],
                    acc1[0][nt][1] + acc1[1][nt][1] + acc1[2][nt][1] + acc1[3][nt][1]);
                *(float2*)&gates1[arow0 + 8][gcl] = make_float2(
                    acc1[0][nt][2] + acc1[1][nt][2] + acc1[2][nt][2] + acc1[3][nt][2],
                    acc1[0][nt][3] + acc1[1][nt][3] + acc1[2][nt][3] + acc1[3][nt][3]);
            }
        }
        __syncthreads();

        // ---- 6. epilogues + publish (bf16 pairs)
        if (t < maxlen) {
            if (t < mylen) {
                float2 gi = *(const float2*)&gates0[eb][ej];
                float2 gf = *(const float2*)&gates0[eb][16 + ej];
                float2 gg = *(const float2*)&gates0[eb][32 + ej];
                float2 go = *(const float2*)&gates0[eb][48 + ej];
                float i0 = sigm(gi.x), i1 = sigm(gi.y);
                float f0 = sigm(gf.x), f1 = sigm(gf.y);
                float g0 = tanhfast(gg.x), g1 = tanhfast(gg.y);
                float o0 = sigm(go.x), o1 = sigm(go.y);
                float cn0 = fmaf(f0, c0.x, i0 * g0);
                float cn1 = fmaf(f1, c0.y, i1 * g1);
                c0 = make_float2(cn0, cn1);
                hmy0 = make_float2(o0 * tanhfast(cn0), o1 * tanhfast(cn1));
            }
            g_h0buf[t & 1][bt][hs][eb][pp8] = packbf(hmy0.x, hmy0.y);
        }
        if (t >= 1) {
            if (t - 1 < mylen) {
                float2 gi = *(const float2*)&gates1[eb][ej];
                float2 gf = *(const float2*)&gates1[eb][16 + ej];
                float2 gg = *(const float2*)&gates1[eb][32 + ej];
                float2 go = *(const float2*)&gates1[eb][48 + ej];
                float i0 = sigm(gi.x), i1 = sigm(gi.y);
                float f0 = sigm(gf.x), f1 = sigm(gf.y);
                float g0 = tanhfast(gg.x), g1 = tanhfast(gg.y);
                float o0 = sigm(go.x), o1 = sigm(go.y);
                float cn0 = fmaf(f0, c1.x, i0 * g0);
                float cn1 = fmaf(f1, c1.y, i1 * g1);
                c1 = make_float2(cn0, cn1);
                hmy1 = make_float2(o0 * tanhfast(cn0), o1 * tanhfast(cn1));
            }
            g_h1buf[(t - 1) & 1][bt][hs][eb][pp8] = packbf(hmy1.x, hmy1.y);
        }
        __syncthreads();

        // ---- 7. single release
        if (tid == 0) {
            unsigned nv = (unsigned)(t + 1);
            asm volatile("st.release.gpu.u32 [%0], %1;" :: "l"(myflag), "r"(nv) : "memory");
        }
    }

    // publish final layer-1 hidden state for FC (f32)
    float* d = g_hfinal + (long long)(bt * 32 + eb) * Hv + hs * 16;
    d[ej] = hmy1.x;
    d[ej + 1] = hmy1.y;
}

// ---------------- final FC + softmax ----------------------------------------
__global__ void fc_softmax(const float* __restrict__ W_fc,
                           const float* __restrict__ b_fc, float* __restrict__ out)
{
    int b = blockIdx.x, lane = threadIdx.x;
    float logit[10];
#pragma unroll
    for (int c = 0; c < 10; c++) {
        float s = 0.0f;
        for (int h = lane; h < Hv; h += 32)
            s += g_hfinal[b * Hv + h] * W_fc[c * Hv + h];
#pragma unroll
        for (int o = 16; o; o >>= 1) s += __shfl_down_sync(0xffffffffu, s, o);
        logit[c] = s;
    }
    if (lane == 0) {
        float mx = -1e30f;
#pragma unroll
        for (int c = 0; c < 10; c++) {
            logit[c] += b_fc[c];
            mx = fmaxf(mx, logit[c]);
        }
        float sum = 0.0f;
#pragma unroll
        for (int c = 0; c < 10; c++) {
            logit[c] = expf(logit[c] - mx);
            sum += logit[c];
        }
        float inv = 1.0f / sum;
#pragma unroll
        for (int c = 0; c < 10; c++) out[b * 10 + c] = logit[c] * inv;
    }
}

// ---------------- host launcher ---------------------------------------------
extern "C" void kernel_launch(void* const* d_in, const int* in_sizes, int n_in,
                              void* d_out, int out_size)
{
    const float* x      = (const float*)d_in[0];
    const int*   length = (const int*)d_in[1];
    const float* W_fc   = (const float*)d_in[2];
    const float* b_fc   = (const float*)d_in[3];
    const float* W_ih0  = (const float*)d_in[4];
    const float* W_hh0  = (const float*)d_in[5];
    const float* b_ih0  = (const float*)d_in[6];
    const float* b_hh0  = (const float*)d_in[7];
    const float* W_ih1  = (const float*)d_in[8];
    const float* W_hh1  = (const float*)d_in[9];
    const float* b_ih1  = (const float*)d_in[10];
    const float* b_hh1  = (const float*)d_in[11];
    float* out = (float*)d_out;

    int smem = 28962 * 4;   // ~113.1 KB
    cudaFuncSetAttribute(lstm_fused, cudaFuncAttributeMaxDynamicSharedMemorySize, smem);

    dim3 ggrid(G4v / 64, (Tv * Bv) / 128);

    // layer 0 input projection: Xg = X @ W_ih0^T + (b_ih0 + b_hh0)
    gemm_tf32<<<ggrid, 256>>>(x, (long long)Tv * Iv, (long long)Iv, Iv,
                              W_ih0, b_ih0, b_hh0);
    // fused 2-layer recurrence (bf16 wavefront): 513 rounds
    lstm_fused<<<128, 256, smem>>>(length, W_hh0, W_ih1, W_hh1, b_ih1, b_hh1);
    // FC + softmax
    fc_softmax<<<Bv, 32>>>(W_fc, b_fc, out);
}

// round 11
// speedup vs baseline: 2.7657x; 1.2462x over previous
#include <cuda_runtime.h>
#include <cstdint>

#define Bv 256
#define Tv 512
#define Iv 128
#define Hv 256

// ---------------- scratch (device globals; no cudaMalloc allowed) ----------
// h exchange buffers, bf16x2 pairs: [buf][group][slice][row(32)][pp(8)]
// pair p (cols 2p,2p+1) stored at pp=(p&3)*2+(p>>2)  (comb for LDS.64 frags)
__device__ __align__(16) unsigned g_h0buf[2][8][16][32][8];
__device__ __align__(16) unsigned g_h1buf[2][8][16][32][8];
__device__ float g_hfinal[Bv * Hv];
__device__ unsigned g_flags[8 * 32];                // one flag per CTA

// ---------------- helpers ---------------------------------------------------
__device__ __forceinline__ unsigned packbf(float lo, float hi) {
    unsigned r;
    asm("cvt.rn.bf16x2.f32 %0, %1, %2;" : "=r"(r) : "f"(hi), "f"(lo));
    return r;
}
__device__ __forceinline__ void mma_bf16(float c[4], unsigned a0, unsigned a1,
                                         unsigned a2, unsigned a3,
                                         unsigned b0, unsigned b1) {
    asm volatile(
        "mma.sync.aligned.m16n8k16.row.col.f32.bf16.bf16.f32 "
        "{%0,%1,%2,%3}, {%4,%5,%6,%7}, {%8,%9}, {%0,%1,%2,%3};"
        : "+f"(c[0]), "+f"(c[1]), "+f"(c[2]), "+f"(c[3])
        : "r"(a0), "r"(a1), "r"(a2), "r"(a3), "r"(b0), "r"(b1));
}
__device__ __forceinline__ float tanhfast(float x) {
    float y;
    asm("tanh.approx.f32 %0, %1;" : "=f"(y) : "f"(x));
    return y;
}
__device__ __forceinline__ float sigm(float x) {
    return fmaf(0.5f, tanhfast(0.5f * x), 0.5f);
}

// ---------------- flag reset (replaces GEMM's reset duty) -------------------
__global__ void resetf() { g_flags[threadIdx.x] = 0u; }

// ---------------- fully fused 2-layer LSTM (bf16 wavefront) -----------------
// 128 CTAs: bt (8 groups of 32 batch rows) x hs (16 H-slices of 16 cols).
// Round t: L0 step t (x(t) projection fused in!) + L1 step t-1.
// SMEM (u32): W1s 16384 | W0i 4096 | Hs0 4096 | Hs1 4096 | Xs 2048 |
//             gates0 2176 | gates1 2176 | misc 34   => ~137.2 KB
__global__ void __launch_bounds__(256, 1) lstm_fused(
    const float* __restrict__ x, const int* __restrict__ lengths,
    const float* __restrict__ W_ih0, const float* __restrict__ W_hh0,
    const float* __restrict__ b_ih0, const float* __restrict__ b_hh0,
    const float* __restrict__ W_ih1, const float* __restrict__ W_hh1,
    const float* __restrict__ b_ih1, const float* __restrict__ b_hh1)
{
    extern __shared__ unsigned smu[];
    unsigned* W1s = smu;                   // [s32][tp8][n8][pp8]
    unsigned* W0i = smu + 16384;           // [s8][tp8][n8][pp8]
    unsigned* Hs0 = smu + 20480;           // [s16][row32][pp8]
    unsigned* Hs1 = smu + 24576;
    unsigned* Xs  = smu + 28672;           // [s8][row32][pp8]
    float (*gates0)[68] = (float(*)[68])(smu + 30720);
    float (*gates1)[68] = (float(*)[68])(smu + 32896);
    int* slen = (int*)(smu + 35072);
    int* pmax = (int*)(smu + 35104);

    int tid = threadIdx.x, lane = tid & 31, wid = tid >> 5;
    int bt = blockIdx.x & 7;
    int hs = blockIdx.x >> 3;
    int wm = wid & 1, wn = wid >> 1;       // 2(M) x 4(N=gate) warps
    int grp = lane >> 2, tig = lane & 3;
    int arow0 = wm * 16 + grp;

    // ---- W_hh0 B-fragments in registers (bf16 pairs)
    unsigned Wr0[2][16][2];
#pragma unroll
    for (int nt = 0; nt < 2; nt++) {
        int n = wn * 256 + hs * 16 + nt * 8 + grp;
        const float* p = W_hh0 + (long long)n * Hv;
#pragma unroll
        for (int s = 0; s < 16; s++) {
            Wr0[nt][s][0] = packbf(__ldg(p + s * 16 + 2 * tig),
                                   __ldg(p + s * 16 + 2 * tig + 1));
            Wr0[nt][s][1] = packbf(__ldg(p + s * 16 + 2 * tig + 8),
                                   __ldg(p + s * 16 + 2 * tig + 9));
        }
    }

    // ---- stage W1 = [W_ih1 | W_hh1] into SMEM (bf16 pairs, frag layout)
    for (int i = tid; i < 16384; i += 256) {
        int s = i >> 9, tp = (i >> 6) & 7, n = (i >> 3) & 7, pp = i & 7;
        int p = (pp >> 1) + ((pp & 1) << 2);
        int R = (tp >> 1) * 256 + hs * 16 + ((tp & 1) << 3) + n;
        int k = s * 16 + 2 * p;
        float lo, hi;
        if (k < 256) { lo = W_ih1[R * 256 + k]; hi = W_ih1[R * 256 + k + 1]; }
        else         { lo = W_hh1[R * 256 + k - 256]; hi = W_hh1[R * 256 + k - 255]; }
        W1s[i] = packbf(lo, hi);
    }
    // ---- stage W_ih0 slice into SMEM (K=128)
    for (int i = tid; i < 4096; i += 256) {
        int s = i >> 9, tp = (i >> 6) & 7, n = (i >> 3) & 7, pp = i & 7;
        int p = (pp >> 1) + ((pp & 1) << 2);
        int R = (tp >> 1) * 256 + hs * 16 + ((tp & 1) << 3) + n;
        int k = s * 16 + 2 * p;
        W0i[i] = packbf(W_ih0[R * Iv + k], W_ih0[R * Iv + k + 1]);
    }
    if (tid < 32) slen[tid] = lengths[bt * 32 + tid];
    __syncthreads();
    if (tid == 0) {
        int m = 0;
        for (int i = 0; i < 32; i++) m = max(m, slen[i]);
        pmax[0] = m;
    }
    __syncthreads();
    int maxlen = pmax[0];

    unsigned* myflag = g_flags + bt * 32 + hs;
    const unsigned* gflag = g_flags + bt * 32;

    // accumulator-mapped biases
    float bs0[2][2], bs1[2][2];
#pragma unroll
    for (int nt = 0; nt < 2; nt++) {
        int col = wn * 256 + hs * 16 + nt * 8 + 2 * tig;
        bs0[nt][0] = b_ih0[col] + b_hh0[col];
        bs0[nt][1] = b_ih0[col + 1] + b_hh0[col + 1];
        bs1[nt][0] = b_ih1[col] + b_hh1[col];
        bs1[nt][1] = b_ih1[col + 1] + b_hh1[col + 1];
    }

    // epilogue mapping: thread owns (eb, cols 2p8, 2p8+1)
    int eb = tid >> 3, p8 = tid & 7, ej = 2 * p8;
    int pp8 = (p8 & 3) * 2 + (p8 >> 2);
    int mylen = slen[eb];
    float2 hmy0 = make_float2(0.f, 0.f), hmy1 = make_float2(0.f, 0.f);
    float2 c0 = make_float2(0.f, 0.f), c1 = make_float2(0.f, 0.f);

    // x staging mapping: thread handles row xrow, pairs p = (tid&7) + 8j
    int xrow = tid >> 3;
    int xpp  = ((tid & 7) & 3) * 2 + ((tid & 7) >> 2);
    const float* xbase = x + (long long)(bt * 32 + xrow) * (Tv * Iv) + 2 * (tid & 7);

    for (int t = 0; t <= maxlen; t++) {
        // ---- 1. LDG x(t) into registers (DRAM/L2 latency hides under wait)
        float2 xr[8];
        if (t < maxlen) {
            const float* xp = xbase + t * Iv;
#pragma unroll
            for (int j = 0; j < 8; j++)
                xr[j] = *(const float2*)(xp + 16 * j);
        }

        // ---- 2. wait: all 16 peers completed round t-1
        if (t > 0) {
            if (tid < 16) {
                const unsigned* fp = gflag + tid;
                unsigned v;
                do {
                    asm volatile("ld.acquire.gpu.u32 %0, [%1];" : "=r"(v) : "l"(fp));
                } while (v < (unsigned)t);
            }
        }
        __syncthreads();

        // ---- 3. stage h tiles + x tile into SMEM
        if (t > 0) {
            const uint4* s4 = (const uint4*)&g_h0buf[(t - 1) & 1][bt][0][0][0];
            uint4* d4 = (uint4*)Hs0;
#pragma unroll
            for (int i = 0; i < 4; i++) d4[tid + i * 256] = s4[tid + i * 256];
        }
        if (t > 1) {
            const uint4* s4 = (const uint4*)&g_h1buf[t & 1][bt][0][0][0];
            uint4* d4 = (uint4*)Hs1;
#pragma unroll
            for (int i = 0; i < 4; i++) d4[tid + i * 256] = s4[tid + i * 256];
        }
        if (t < maxlen) {
#pragma unroll
            for (int j = 0; j < 8; j++)
                Xs[j * 256 + xrow * 8 + xpp] = packbf(xr[j].x, xr[j].y);
        }
        __syncthreads();

        // ---- 4. mma phase (bf16 k16; split accumulator chains)
        float acc0[2][2][4];
        float acc1[4][2][4];
#pragma unroll
        for (int nt = 0; nt < 2; nt++) {
            acc0[0][nt][0] = bs0[nt][0]; acc0[0][nt][1] = bs0[nt][1];
            acc0[0][nt][2] = bs0[nt][0]; acc0[0][nt][3] = bs0[nt][1];
            acc0[1][nt][0] = 0.f; acc0[1][nt][1] = 0.f;
            acc0[1][nt][2] = 0.f; acc0[1][nt][3] = 0.f;
            acc1[0][nt][0] = bs1[nt][0]; acc1[0][nt][1] = bs1[nt][1];
            acc1[0][nt][2] = bs1[nt][0]; acc1[0][nt][3] = bs1[nt][1];
#pragma unroll
            for (int ch = 1; ch < 4; ch++) {
                acc1[ch][nt][0] = 0.f; acc1[ch][nt][1] = 0.f;
                acc1[ch][nt][2] = 0.f; acc1[ch][nt][3] = 0.f;
            }
        }

        // L0 input projection: x(t) @ W_ih0^T  (8 k-steps)
        if (t < maxlen) {
#pragma unroll
            for (int s = 0; s < 8; s++) {
                uint2 lo = *(const uint2*)&Xs[s * 256 + arow0 * 8 + 2 * tig];
                uint2 hi = *(const uint2*)&Xs[s * 256 + (arow0 + 8) * 8 + 2 * tig];
#pragma unroll
                for (int nt = 0; nt < 2; nt++) {
                    uint2 wb = *(const uint2*)
                        &W0i[((s * 8 + wn * 2 + nt) * 8 + grp) * 8 + 2 * tig];
                    mma_bf16(acc0[s & 1][nt], lo.x, hi.x, lo.y, hi.y, wb.x, wb.y);
                }
            }
        }
        // h0(t-1): feeds L0 recurrent part AND L1 input part
        if (t > 0) {
#pragma unroll
            for (int s = 0; s < 16; s++) {
                uint2 lo = *(const uint2*)&Hs0[s * 256 + arow0 * 8 + 2 * tig];
                uint2 hi = *(const uint2*)&Hs0[s * 256 + (arow0 + 8) * 8 + 2 * tig];
#pragma unroll
                for (int nt = 0; nt < 2; nt++) {
                    mma_bf16(acc0[s & 1][nt], lo.x, hi.x, lo.y, hi.y,
                             Wr0[nt][s][0], Wr0[nt][s][1]);
                    uint2 wb = *(const uint2*)
                        &W1s[((s * 8 + wn * 2 + nt) * 8 + grp) * 8 + 2 * tig];
                    mma_bf16(acc1[s & 1][nt], lo.x, hi.x, lo.y, hi.y, wb.x, wb.y);
                }
            }
        }
        // h1(t-2) against W_hh1
        if (t > 1) {
#pragma unroll
            for (int s = 0; s < 16; s++) {
                uint2 lo = *(const uint2*)&Hs1[s * 256 + arow0 * 8 + 2 * tig];
                uint2 hi = *(const uint2*)&Hs1[s * 256 + (arow0 + 8) * 8 + 2 * tig];
#pragma unroll
                for (int nt = 0; nt < 2; nt++) {
                    uint2 wb = *(const uint2*)
                        &W1s[(((16 + s) * 8 + wn * 2 + nt) * 8 + grp) * 8 + 2 * tig];
                    mma_bf16(acc1[2 + (s & 1)][nt], lo.x, hi.x, lo.y, hi.y, wb.x, wb.y);
                }
            }
        }

        // ---- 5. write gate preacts
#pragma unroll
        for (int nt = 0; nt < 2; nt++) {
            int gcl = wn * 16 + nt * 8 + 2 * tig;
            if (t < maxlen) {
                *(float2*)&gates0[arow0][gcl] = make_float2(
                    acc0[0][nt][0] + acc0[1][nt][0],
                    acc0[0][nt][1] + acc0[1][nt][1]);
                *(float2*)&gates0[arow0 + 8][gcl] = make_float2(
                    acc0[0][nt][2] + acc0[1][nt][2],
                    acc0[0][nt][3] + acc0[1][nt][3]);
            }
            if (t >= 1) {
                *(float2*)&gates1[arow0][gcl] = make_float2(
                    acc1[0][nt][0] + acc1[1][nt][0] + acc1[2][nt][0] + acc1[3][nt][0],
                    acc1[0][nt][1] + acc1[1][nt][1] + acc1[2][nt][1] + acc1[3][nt][1]);
                *(float2*)&gates1[arow0 + 8][gcl] = make_float2(
                    acc1[0][nt][2] + acc1[1][nt][2] + acc1[2][nt][2] + acc1[3][nt][2],
                    acc1[0][nt][3] + acc1[1][nt][3] + acc1[2][nt][3] + acc1[3][nt][3]);
            }
        }
        __syncthreads();

        // ---- 6. epilogues + publish (bf16 pairs)
        if (t < maxlen) {
            if (t < mylen) {
                float2 gi = *(const float2*)&gates0[eb][ej];
                float2 gf = *(const float2*)&gates0[eb][16 + ej];
                float2 gg = *(const float2*)&gates0[eb][32 + ej];
                float2 go = *(const float2*)&gates0[eb][48 + ej];
                float i0 = sigm(gi.x), i1 = sigm(gi.y);
                float f0 = sigm(gf.x), f1 = sigm(gf.y);
                float g0 = tanhfast(gg.x), g1 = tanhfast(gg.y);
                float o0 = sigm(go.x), o1 = sigm(go.y);
                float cn0 = fmaf(f0, c0.x, i0 * g0);
                float cn1 = fmaf(f1, c0.y, i1 * g1);
                c0 = make_float2(cn0, cn1);
                hmy0 = make_float2(o0 * tanhfast(cn0), o1 * tanhfast(cn1));
            }
            g_h0buf[t & 1][bt][hs][eb][pp8] = packbf(hmy0.x, hmy0.y);
        }
        if (t >= 1) {
            if (t - 1 < mylen) {
                float2 gi = *(const float2*)&gates1[eb][ej];
                float2 gf = *(const float2*)&gates1[eb][16 + ej];
                float2 gg = *(const float2*)&gates1[eb][32 + ej];
                float2 go = *(const float2*)&gates1[eb][48 + ej];
                float i0 = sigm(gi.x), i1 = sigm(gi.y);
                float f0 = sigm(gf.x), f1 = sigm(gf.y);
                float g0 = tanhfast(gg.x), g1 = tanhfast(gg.y);
                float o0 = sigm(go.x), o1 = sigm(go.y);
                float cn0 = fmaf(f0, c1.x, i0 * g0);
                float cn1 = fmaf(f1, c1.y, i1 * g1);
                c1 = make_float2(cn0, cn1);
                hmy1 = make_float2(o0 * tanhfast(cn0), o1 * tanhfast(cn1));
            }
            g_h1buf[(t - 1) & 1][bt][hs][eb][pp8] = packbf(hmy1.x, hmy1.y);
        }
        __syncthreads();

        // ---- 7. single release
        if (tid == 0) {
            unsigned nv = (unsigned)(t + 1);
            asm volatile("st.release.gpu.u32 [%0], %1;" :: "l"(myflag), "r"(nv) : "memory");
        }
    }

    // publish final layer-1 hidden state for FC (f32)
    float* d = g_hfinal + (long long)(bt * 32 + eb) * Hv + hs * 16;
    d[ej] = hmy1.x;
    d[ej + 1] = hmy1.y;
}

// ---------------- final FC + softmax ----------------------------------------
__global__ void fc_softmax(const float* __restrict__ W_fc,
                           const float* __restrict__ b_fc, float* __restrict__ out)
{
    int b = blockIdx.x, lane = threadIdx.x;
    float logit[10];
#pragma unroll
    for (int c = 0; c < 10; c++) {
        float s = 0.0f;
        for (int h = lane; h < Hv; h += 32)
            s += g_hfinal[b * Hv + h] * W_fc[c * Hv + h];
#pragma unroll
        for (int o = 16; o; o >>= 1) s += __shfl_down_sync(0xffffffffu, s, o);
        logit[c] = s;
    }
    if (lane == 0) {
        float mx = -1e30f;
#pragma unroll
        for (int c = 0; c < 10; c++) {
            logit[c] += b_fc[c];
            mx = fmaxf(mx, logit[c]);
        }
        float sum = 0.0f;
#pragma unroll
        for (int c = 0; c < 10; c++) {
            logit[c] = expf(logit[c] - mx);
            sum += logit[c];
        }
        float inv = 1.0f / sum;
#pragma unroll
        for (int c = 0; c < 10; c++) out[b * 10 + c] = logit[c] * inv;
    }
}

// ---------------- host launcher ---------------------------------------------
extern "C" void kernel_launch(void* const* d_in, const int* in_sizes, int n_in,
                              void* d_out, int out_size)
{
    const float* x      = (const float*)d_in[0];
    const int*   length = (const int*)d_in[1];
    const float* W_fc   = (const float*)d_in[2];
    const float* b_fc   = (const float*)d_in[3];
    const float* W_ih0  = (const float*)d_in[4];
    const float* W_hh0  = (const float*)d_in[5];
    const float* b_ih0  = (const float*)d_in[6];
    const float* b_hh0  = (const float*)d_in[7];
    const float* W_ih1  = (const float*)d_in[8];
    const float* W_hh1  = (const float*)d_in[9];
    const float* b_ih1  = (const float*)d_in[10];
    const float* b_hh1  = (const float*)d_in[11];
    float* out = (float*)d_out;

    int smem = 35106 * 4;   // ~137.1 KB
    cudaFuncSetAttribute(lstm_fused, cudaFuncAttributeMaxDynamicSharedMemorySize, smem);

    // reset exchange flags (graph-replay safe)
    resetf<<<1, 256>>>();
    // fully fused 2-layer LSTM (513 wavefront rounds, no precomputed xg)
    lstm_fused<<<128, 256, smem>>>(x, length, W_ih0, W_hh0, b_ih0, b_hh0,
                                   W_ih1, W_hh1, b_ih1, b_hh1);
    // FC + softmax
    fc_softmax<<<Bv, 32>>>(W_fc, b_fc, out);
}